// round 11
// baseline (speedup 1.0000x reference)
#include <cuda_runtime.h>
#include <cuda_fp16.h>
#include <math.h>
#include <stdint.h>

// ---------------------------------------------------------------------------
// RelationalMemoryCell  (B=2048, S=8, H=8, M=1024, QKV=384, TOT=3072)
// Round 11: fp16 HMMA GEMM at 2 CTAs/SM.
//   64x128 CTA tile, 256 threads (8 warps, 2x4), BK=32, 4-stage cp.async,
//   __launch_bounds__(256, 2) -> two independent barrier domains per SM.
// ---------------------------------------------------------------------------

#define B_     2048
#define S_     8
#define H_     8
#define M_     1024
#define QKV_   384
#define TOT_   3072
#define SP1_   9
#define ROWS_  (B_*SP1_)   // 18432

typedef __half  fp16;
typedef __half2 fp162;

// ---- global scratch (allocation-free rule) ----
__device__ __align__(256) float g_x   [(size_t)B_   * M_  ];
__device__ __align__(256) float g_m1f [(size_t)ROWS_* M_  ];
__device__ __align__(256) float g_m2  [(size_t)ROWS_* M_  ];
__device__ __align__(256) float g_gi  [(size_t)B_ * 2];

__device__ __align__(256) fp16 g_qkv_h [(size_t)ROWS_ * TOT_];
__device__ __align__(256) fp16 g_in_h  [(size_t)B_ * M_];
// weights arena (fp16): k_in @0 (1M), k_qkv @1M (3M), mlp_k0 @4M, mlp_k1 @5M
__device__ __align__(256) fp16 g_w     [(size_t)6 * M_ * M_];
__device__ __align__(256) fp16 g_mpi_h [(size_t)ROWS_ * M_];
__device__ __align__(256) fp16 g_m1_h  [(size_t)ROWS_ * M_];
__device__ __align__(256) fp16 g_h_h   [(size_t)ROWS_ * M_];

// ---------------------------------------------------------------------------
// helpers
// ---------------------------------------------------------------------------
__device__ __forceinline__ uint32_t smem_u32(const void* p) {
    uint32_t a;
    asm("{ .reg .u64 t; cvta.to.shared.u64 t, %1; cvt.u32.u64 %0, t; }"
        : "=r"(a) : "l"(p));
    return a;
}
__device__ __forceinline__ void cp16(uint32_t dst, const void* src) {
    asm volatile("cp.async.cg.shared.global [%0], [%1], 16;"
                 :: "r"(dst), "l"(src) : "memory");
}
#define CP_COMMIT() asm volatile("cp.async.commit_group;" ::: "memory")
#define CP_WAIT()   asm volatile("cp.async.wait_group 2;"  ::: "memory")

__device__ __forceinline__ void ldsm4(uint32_t* r, uint32_t a) {
    asm volatile("ldmatrix.sync.aligned.m8n8.x4.shared.b16 {%0,%1,%2,%3}, [%4];"
        : "=r"(r[0]), "=r"(r[1]), "=r"(r[2]), "=r"(r[3]) : "r"(a));
}
__device__ __forceinline__ void ldsm4t(uint32_t* r, uint32_t a) {
    asm volatile("ldmatrix.sync.aligned.m8n8.x4.trans.shared.b16 {%0,%1,%2,%3}, [%4];"
        : "=r"(r[0]), "=r"(r[1]), "=r"(r[2]), "=r"(r[3]) : "r"(a));
}
__device__ __forceinline__ void mma16816(float* c, const uint32_t* a, const uint32_t* b) {
    asm volatile(
        "mma.sync.aligned.m16n8k16.row.col.f32.f16.f16.f32 "
        "{%0,%1,%2,%3}, {%4,%5,%6,%7}, {%8,%9}, {%0,%1,%2,%3};"
        : "+f"(c[0]), "+f"(c[1]), "+f"(c[2]), "+f"(c[3])
        : "r"(a[0]), "r"(a[1]), "r"(a[2]), "r"(a[3]), "r"(b[0]), "r"(b[1]));
}

// ---------------------------------------------------------------------------
// cvt_kernel: fp32 -> fp16, vectorized by 4.
// ---------------------------------------------------------------------------
__global__ void cvt_kernel(const float* __restrict__ src,
                           fp16* __restrict__ dst, int n4)
{
    int i = blockIdx.x * blockDim.x + threadIdx.x;
    if (i >= n4) return;
    float4 v = __ldg((const float4*)src + i);
    fp162* D = (fp162*)dst + 2 * i;
    D[0] = __floats2half2_rn(v.x, v.y);
    D[1] = __floats2half2_rn(v.z, v.w);
}

// ---------------------------------------------------------------------------
// fp16 HMMA GEMM, 256 threads (8 warps, 2x4 grid, 32x32 warp tile),
// 64x128 CTA tile, BK=32, 4-stage cp.async, 2 CTAs/SM.
// MODE 0: fp32 out (+bias)
// MODE 1: relu(+bias) -> fp16 out (Ch)
// MODE 2: fp32 out = Rf + (+bias)
// MODE 3: fp16 out (+bias)
// SMEM per buffer: A 64x80B @0 (5120), B 32x272B @5120 (8704) = 13824 B
// ---------------------------------------------------------------------------
#define AST     80u
#define BST     272u
#define OFF_B   5120u
#define BUFSZ   13824u
#define NSTAGE  4
#define DSMEM   (NSTAGE * 13824)

template<int MODE>
__global__ __launch_bounds__(256, 2)
void hgemm_kernel(const fp16* __restrict__ Ah, const fp16* __restrict__ Bh,
                  const float* __restrict__ bias,
                  const float* __restrict__ Rf,
                  float* __restrict__ Cf, fp16* __restrict__ Ch,
                  int N, int K)
{
    extern __shared__ char sm_[];
    const uint32_t sbase = smem_u32(sm_);

    const int tid  = threadIdx.x;
    const int wid  = tid >> 5;
    const int lane = tid & 31;
    const int wm   = (wid & 1) << 5;     // 0,32
    const int wn   = (wid >> 1) << 5;    // 0,32,64,96
    const int bm   = blockIdx.y << 6;    // 64-row tiles
    const int bn   = blockIdx.x << 7;

    // loader slots: A 64 rows x 4 segs of 16B (256, 1 each);
    //               B 32 rows x 16 segs of 16B (512, 2 each: rows brow, brow+16)
    const int arow = tid >> 2, aseg = tid & 3;
    const int brow = tid >> 4, bseg = tid & 15;

    const fp16* Ap = Ah + (size_t)(bm + arow) * K + (aseg << 3);
    const fp16* Bp = Bh + (size_t)brow * N + bn + (bseg << 3);
    const uint32_t aDst  = (uint32_t)arow * AST + (uint32_t)(aseg << 4);
    const uint32_t bDst  = (uint32_t)brow * BST + (uint32_t)(bseg << 4);
    const size_t  bRow2  = (size_t)16 * N;
    const uint32_t bDst2 = bDst + 16u * BST;

    const int nchunk = K >> 5;

    float acc[2][4][4];
    #pragma unroll
    for (int i = 0; i < 2; i++)
        #pragma unroll
        for (int j = 0; j < 4; j++)
            #pragma unroll
            for (int k = 0; k < 4; k++) acc[i][j][k] = 0.f;

    // prologue: stages 0..NSTAGE-2
    #pragma unroll
    for (int s = 0; s < NSTAGE - 1; s++) {
        const uint32_t sb = sbase + (uint32_t)s * BUFSZ;
        cp16(sb + aDst,          Ap + (s << 5));
        cp16(sb + OFF_B + bDst,  Bp + (size_t)(s << 5) * N);
        cp16(sb + OFF_B + bDst2, Bp + bRow2 + (size_t)(s << 5) * N);
        CP_COMMIT();
    }

    const uint32_t aOffBase = (uint32_t)(wm + (lane & 15)) * AST
                            + (uint32_t)((lane >> 4) << 4);
    const uint32_t bOffBase = (uint32_t)(lane & 15) * BST
                            + (uint32_t)(wn << 1) + (uint32_t)((lane >> 4) << 4);

    #pragma unroll 1
    for (int c = 0; c < nchunk; c++) {
        CP_WAIT();
        __syncthreads();

        const uint32_t tb = sbase + (uint32_t)(c % NSTAGE) * BUFSZ;

        #pragma unroll
        for (int ks = 0; ks < 2; ks++) {
            uint32_t ra[2][4], rb[2][4];
            const uint32_t aAd = tb + aOffBase + (uint32_t)(ks << 5);
            ldsm4(ra[0], aAd);
            ldsm4(ra[1], aAd + 16u * AST);
            const uint32_t bAd = tb + OFF_B + bOffBase + (uint32_t)(ks << 4) * BST;
            ldsm4t(rb[0], bAd);
            ldsm4t(rb[1], bAd + 32u);
            #pragma unroll
            for (int mt = 0; mt < 2; mt++)
                #pragma unroll
                for (int nt = 0; nt < 4; nt++)
                    mma16816(acc[mt][nt], ra[mt], &rb[nt >> 1][(nt & 1) << 1]);
        }

        // issue stage c + NSTAGE-1
        const int cn = c + NSTAGE - 1;
        if (cn < nchunk) {
            const uint32_t nb = sbase + (uint32_t)(cn % NSTAGE) * BUFSZ;
            cp16(nb + aDst,          Ap + (cn << 5));
            cp16(nb + OFF_B + bDst,  Bp + (size_t)(cn << 5) * N);
            cp16(nb + OFF_B + bDst2, Bp + bRow2 + (size_t)(cn << 5) * N);
        }
        CP_COMMIT();
    }

    // ---- epilogue ----
    #pragma unroll
    for (int mt = 0; mt < 2; mt++) {
        #pragma unroll
        for (int nt = 0; nt < 4; nt++) {
            const int m = bm + wm + (mt << 4) + (lane >> 2);
            const int n = bn + wn + (nt << 3) + ((lane & 3) << 1);
            const float b0 = __ldg(&bias[n]);
            const float b1 = __ldg(&bias[n + 1]);
            float2 v0, v1;
            v0.x = acc[mt][nt][0] + b0;  v0.y = acc[mt][nt][1] + b1;
            v1.x = acc[mt][nt][2] + b0;  v1.y = acc[mt][nt][3] + b1;
            const size_t i0 = (size_t)m * N + n;
            const size_t i1 = (size_t)(m + 8) * N + n;
            if (MODE == 0) {
                *(float2*)(Cf + i0) = v0;
                *(float2*)(Cf + i1) = v1;
            }
            if (MODE == 1) {
                v0.x = fmaxf(v0.x, 0.f); v0.y = fmaxf(v0.y, 0.f);
                v1.x = fmaxf(v1.x, 0.f); v1.y = fmaxf(v1.y, 0.f);
                *(fp162*)(Ch + i0) = __floats2half2_rn(v0.x, v0.y);
                *(fp162*)(Ch + i1) = __floats2half2_rn(v1.x, v1.y);
            }
            if (MODE == 2) {
                float2 r0 = *(const float2*)(Rf + i0);
                float2 r1 = *(const float2*)(Rf + i1);
                v0.x += r0.x; v0.y += r0.y;
                v1.x += r1.x; v1.y += r1.y;
                *(float2*)(Cf + i0) = v0;
                *(float2*)(Cf + i1) = v1;
            }
            if (MODE == 3) {
                *(fp162*)(Ch + i0) = __floats2half2_rn(v0.x, v0.y);
                *(fp162*)(Ch + i1) = __floats2half2_rn(v1.x, v1.y);
            }
        }
    }
}

// ---------------------------------------------------------------------------
// mpi_h = fp16(concat(memory, x))
// ---------------------------------------------------------------------------
__global__ void build_mpi_kernel(const float* __restrict__ mem,
                                 const float* __restrict__ x,
                                 fp16* __restrict__ hi)
{
    size_t i = (size_t)blockIdx.x * blockDim.x + threadIdx.x;  // pair index
    int    mp  = (int)(i & 511);
    size_t row = i >> 9;
    size_t b   = row / SP1_;
    int    s   = (int)(row - b * SP1_);
    const float* src = (s < S_) ? (mem + ((b * S_ + s) << 10)) : (x + (b << 10));
    float2 v = *(const float2*)(src + (mp << 1));
    ((fp162*)hi)[i] = __floats2half2_rn(v.x, v.y);
}

// ---------------------------------------------------------------------------
// gi[b,0:2] = x[b,:] @ kernel_gi + bias_gi
// ---------------------------------------------------------------------------
__global__ void gi_kernel(const float* __restrict__ x,
                          const float* __restrict__ kgi,
                          const float* __restrict__ bgi,
                          float* __restrict__ gi)
{
    int b    = blockIdx.x * 8 + (threadIdx.x >> 5);
    int lane = threadIdx.x & 31;
    const float* xr = x + (size_t)b * M_;
    float g0 = 0.f, g1 = 0.f;
    for (int m = lane; m < M_; m += 32) {
        float xv = xr[m];
        g0 = fmaf(xv, kgi[2 * m + 0], g0);
        g1 = fmaf(xv, kgi[2 * m + 1], g1);
    }
    #pragma unroll
    for (int o = 16; o; o >>= 1) {
        g0 += __shfl_xor_sync(0xffffffffu, g0, o);
        g1 += __shfl_xor_sync(0xffffffffu, g1, o);
    }
    if (lane == 0) {
        gi[2 * b + 0] = g0 + bgi[0];
        gi[2 * b + 1] = g1 + bgi[1];
    }
}

// ---------------------------------------------------------------------------
// Attention per (b,h): m1 = res + softmax(q k^T) v   (qkv in fp16)
// ---------------------------------------------------------------------------
__global__ __launch_bounds__(256)
void attn_kernel(const fp16* __restrict__ qkv,
                 const float* __restrict__ mem,
                 const float* __restrict__ x,
                 fp16* __restrict__ m1h, float* __restrict__ m1f)
{
    const int bh = blockIdx.x;
    const int b  = bh >> 3;
    const int h  = bh & 7;

    __shared__ float q [SP1_][128];
    __shared__ float kk[SP1_][128];
    __shared__ float vv[SP1_][128];
    __shared__ float sc[SP1_][SP1_];

    const float scale = rsqrtf((float)QKV_);
    const int tid = threadIdx.x;

    for (int i = tid; i < SP1_ * 64; i += 256) {
        int s = i >> 6, d = (i & 63) << 1;
        const fp16* base = qkv + ((size_t)(b * SP1_ + s)) * TOT_ + h * QKV_;
        fp162 qv = *(const fp162*)(base + d);
        fp162 kv = *(const fp162*)(base + 128 + d);
        fp162 vv2 = *(const fp162*)(base + 256 + d);
        q [s][d]     = __half2float(qv.x) * scale;
        q [s][d + 1] = __half2float(qv.y) * scale;
        kk[s][d]     = __half2float(kv.x);
        kk[s][d + 1] = __half2float(kv.y);
        vv[s][d]     = __half2float(vv2.x);
        vv[s][d + 1] = __half2float(vv2.y);
    }
    __syncthreads();

    const int w = tid >> 5, lane = tid & 31;
    for (int idx = w; idx < SP1_ * SP1_; idx += 8) {
        int i = idx / SP1_, j = idx - i * SP1_;
        float s = 0.f;
        for (int d = lane; d < 128; d += 32) s = fmaf(q[i][d], kk[j][d], s);
        #pragma unroll
        for (int o = 16; o; o >>= 1) s += __shfl_xor_sync(0xffffffffu, s, o);
        if (lane == 0) sc[i][j] = s;
    }
    __syncthreads();

    if (tid < SP1_) {
        float mx = -1e30f;
        #pragma unroll
        for (int j = 0; j < SP1_; j++) mx = fmaxf(mx, sc[tid][j]);
        float e[SP1_], sum = 0.f;
        #pragma unroll
        for (int j = 0; j < SP1_; j++) { e[j] = expf(sc[tid][j] - mx); sum += e[j]; }
        float inv = 1.f / sum;
        #pragma unroll
        for (int j = 0; j < SP1_; j++) sc[tid][j] = e[j] * inv;
    }
    __syncthreads();

    for (int i = tid; i < SP1_ * 64; i += 256) {
        int s  = i >> 6;
        int d  = (i & 63) << 1;
        float a0 = 0.f, a1 = 0.f;
        #pragma unroll
        for (int j = 0; j < SP1_; j++) {
            a0 = fmaf(sc[s][j], vv[j][d],     a0);
            a1 = fmaf(sc[s][j], vv[j][d + 1], a1);
        }
        const float* src = (s < S_) ? (mem + (((size_t)b * S_ + s) << 10))
                                    : (x + ((size_t)b << 10));
        float2 r = *(const float2*)(src + h * 128 + d);
        float v0 = r.x + a0;
        float v1 = r.y + a1;
        size_t o = ((size_t)(b * SP1_ + s)) * M_ + h * 128 + d;
        *(fp162*)(m1h + o) = __floats2half2_rn(v0, v1);
        *(float2*)(m1f + o) = make_float2(v0, v1);
    }
}

// ---------------------------------------------------------------------------
// Gate epilogue per (b,s)
// ---------------------------------------------------------------------------
__global__ __launch_bounds__(256)
void gate_kernel(const float* __restrict__ mem,
                 const float* __restrict__ m2,
                 const float* __restrict__ kgm,
                 const float* __restrict__ bgm,
                 const float* __restrict__ gi,
                 float* __restrict__ out)
{
    const int bs = blockIdx.x;
    const int b  = bs >> 3;
    const int s  = bs & 7;
    const int tid = threadIdx.x;

    const float* mrow  = mem + (size_t)bs * M_;
    const float* m2row = m2  + ((size_t)(b * SP1_ + s)) * M_;

    float g0 = 0.f, g1 = 0.f;
    for (int m = tid; m < M_; m += 256) {
        float t = tanhf(mrow[m]);
        g0 = fmaf(t, kgm[2 * m + 0], g0);
        g1 = fmaf(t, kgm[2 * m + 1], g1);
    }
    #pragma unroll
    for (int o = 16; o; o >>= 1) {
        g0 += __shfl_xor_sync(0xffffffffu, g0, o);
        g1 += __shfl_xor_sync(0xffffffffu, g1, o);
    }
    __shared__ float s0[8], s1[8];
    __shared__ float igs, fgs;
    int w = tid >> 5, lane = tid & 31;
    if (lane == 0) { s0[w] = g0; s1[w] = g1; }
    __syncthreads();
    if (tid == 0) {
        float G0 = 0.f, G1 = 0.f;
        #pragma unroll
        for (int i = 0; i < 8; i++) { G0 += s0[i]; G1 += s1[i]; }
        G0 += bgm[0] + gi[2 * b + 0];
        G1 += bgm[1] + gi[2 * b + 1] + 1.0f;
        igs = 1.f / (1.f + expf(-G0));
        fgs = 1.f / (1.f + expf(-G1));
    }
    __syncthreads();
    const float ig = igs, fg = fgs;

    float* orow = out + (size_t)b * (S_ * M_) + s * M_;
    for (int m = tid; m < M_; m += 256) {
        orow[m] = fmaf(ig, tanhf(m2row[m]), fg * mrow[m]);
    }
}

// ---------------------------------------------------------------------------
// kernel_launch
// ---------------------------------------------------------------------------
extern "C" void kernel_launch(void* const* d_in, const int* in_sizes, int n_in,
                              void* d_out, int out_size)
{
    const float* inputs   = (const float*)d_in[0];
    const float* memory   = (const float*)d_in[1];
    const float* k_qkv    = (const float*)d_in[2];
    const float* b_qkv    = (const float*)d_in[3];
    const float* k_gi     = (const float*)d_in[4];
    const float* b_gi     = (const float*)d_in[5];
    const float* k_gm     = (const float*)d_in[6];
    const float* b_gm     = (const float*)d_in[7];
    const float* k_in     = (const float*)d_in[8];
    const float* b_in     = (const float*)d_in[9];
    const float* mlp_k0   = (const float*)d_in[10];
    const float* mlp_b0   = (const float*)d_in[11];
    const float* mlp_k1   = (const float*)d_in[12];
    const float* mlp_b1   = (const float*)d_in[13];
    float* out = (float*)d_out;

    float *px, *pm1f, *pm2, *pgi;
    fp16 *pqkvh, *pinh, *pw, *pmpih, *pm1h, *phh;
    cudaGetSymbolAddress((void**)&px,    g_x);
    cudaGetSymbolAddress((void**)&pm1f,  g_m1f);
    cudaGetSymbolAddress((void**)&pm2,   g_m2);
    cudaGetSymbolAddress((void**)&pgi,   g_gi);
    cudaGetSymbolAddress((void**)&pqkvh, g_qkv_h);
    cudaGetSymbolAddress((void**)&pinh,  g_in_h);
    cudaGetSymbolAddress((void**)&pw,    g_w);
    cudaGetSymbolAddress((void**)&pmpih, g_mpi_h);
    cudaGetSymbolAddress((void**)&pm1h,  g_m1_h);
    cudaGetSymbolAddress((void**)&phh,   g_h_h);

    const size_t MM = (size_t)M_ * M_;
    fp16 *kinW = pw;
    fp16 *kqkW = pw + MM;
    fp16 *k0W  = pw + 4 * MM;
    fp16 *k1W  = pw + 5 * MM;

    cudaFuncSetAttribute(hgemm_kernel<0>, cudaFuncAttributeMaxDynamicSharedMemorySize, DSMEM);
    cudaFuncSetAttribute(hgemm_kernel<1>, cudaFuncAttributeMaxDynamicSharedMemorySize, DSMEM);
    cudaFuncSetAttribute(hgemm_kernel<2>, cudaFuncAttributeMaxDynamicSharedMemorySize, DSMEM);
    cudaFuncSetAttribute(hgemm_kernel<3>, cudaFuncAttributeMaxDynamicSharedMemorySize, DSMEM);

    // 0. convert inputs + weights to fp16
    cvt_kernel<<<(B_ * M_ / 4 + 255) / 256, 256>>>(inputs, pinh, B_ * M_ / 4);
    cvt_kernel<<<(int)((MM / 4 + 255) / 256), 256>>>(k_in,   kinW, (int)(MM / 4));
    cvt_kernel<<<(int)((3 * MM / 4 + 255) / 256), 256>>>(k_qkv, kqkW, (int)(3 * MM / 4));
    cvt_kernel<<<(int)((MM / 4 + 255) / 256), 256>>>(mlp_k0, k0W, (int)(MM / 4));
    cvt_kernel<<<(int)((MM / 4 + 255) / 256), 256>>>(mlp_k1, k1W, (int)(MM / 4));

    // 1. x = inputs @ kernel_in + bias_in   (fp32 out — feeds gi + residuals)
    hgemm_kernel<0><<<dim3(M_ / 128, B_ / 64), 256, DSMEM>>>(
        pinh, kinW, b_in, nullptr, px, nullptr, M_, M_);

    // 2. mpi (fp16)
    build_mpi_kernel<<<(unsigned)(((size_t)ROWS_ * M_ / 2) / 256), 256>>>(
        memory, px, pmpih);

    // 3. gi
    gi_kernel<<<B_ / 8, 256>>>(px, k_gi, b_gi, pgi);

    // 4. qkv = mpi @ kernel_qkv + bias_qkv   (fp16 out)
    hgemm_kernel<3><<<dim3(TOT_ / 128, ROWS_ / 64), 256, DSMEM>>>(
        pmpih, kqkW, b_qkv, nullptr, nullptr, pqkvh, TOT_, M_);

    // 5. attention + fp32 residual -> m1 (fp16 + fp32)
    attn_kernel<<<B_ * H_, 256>>>(pqkvh, memory, px, pm1h, pm1f);

    // 6. h = relu(m1 @ mlp_k0 + mlp_b0) -> fp16
    hgemm_kernel<1><<<dim3(M_ / 128, ROWS_ / 64), 256, DSMEM>>>(
        pm1h, k0W, mlp_b0, nullptr, nullptr, phh, M_, M_);

    // 7. m2 = m1(fp32) + h @ mlp_k1 + mlp_b1
    hgemm_kernel<2><<<dim3(M_ / 128, ROWS_ / 64), 256, DSMEM>>>(
        phh, k1W, mlp_b1, pm1f, pm2, nullptr, M_, M_);

    // 8. gates + output
    gate_kernel<<<B_ * S_, 256>>>(memory, pm2, k_gm, b_gm, pgi, out);
}

// round 12
// speedup vs baseline: 1.1038x; 1.1038x over previous
#include <cuda_runtime.h>
#include <cuda_fp16.h>
#include <math.h>
#include <stdint.h>

// ---------------------------------------------------------------------------
// RelationalMemoryCell  (B=2048, S=8, H=8, M=1024, QKV=384, TOT=3072)
// Round 12: R10 base + operand register double-buffer (ldsm(ks+1) issued
// before MMA(ks)) + fused single cvt launch.
// ---------------------------------------------------------------------------

#define B_     2048
#define S_     8
#define H_     8
#define M_     1024
#define QKV_   384
#define TOT_   3072
#define SP1_   9
#define ROWS_  (B_*SP1_)   // 18432

typedef __half  fp16;
typedef __half2 fp162;

// ---- global scratch (allocation-free rule) ----
__device__ __align__(256) float g_x   [(size_t)B_   * M_  ];
__device__ __align__(256) float g_m1f [(size_t)ROWS_* M_  ];
__device__ __align__(256) float g_m2  [(size_t)ROWS_* M_  ];
__device__ __align__(256) float g_gi  [(size_t)B_ * 2];

__device__ __align__(256) fp16 g_qkv_h [(size_t)ROWS_ * TOT_];
__device__ __align__(256) fp16 g_in_h  [(size_t)B_ * M_];
// weights arena (fp16): k_in @0 (1M), k_qkv @1M (3M), mlp_k0 @4M, mlp_k1 @5M
__device__ __align__(256) fp16 g_w     [(size_t)6 * M_ * M_];
__device__ __align__(256) fp16 g_mpi_h [(size_t)ROWS_ * M_];
__device__ __align__(256) fp16 g_m1_h  [(size_t)ROWS_ * M_];
__device__ __align__(256) fp16 g_h_h   [(size_t)ROWS_ * M_];

// ---------------------------------------------------------------------------
// helpers
// ---------------------------------------------------------------------------
__device__ __forceinline__ uint32_t smem_u32(const void* p) {
    uint32_t a;
    asm("{ .reg .u64 t; cvta.to.shared.u64 t, %1; cvt.u32.u64 %0, t; }"
        : "=r"(a) : "l"(p));
    return a;
}
__device__ __forceinline__ void cp16(uint32_t dst, const void* src) {
    asm volatile("cp.async.cg.shared.global [%0], [%1], 16;"
                 :: "r"(dst), "l"(src) : "memory");
}
#define CP_COMMIT() asm volatile("cp.async.commit_group;" ::: "memory")
#define CP_WAIT()   asm volatile("cp.async.wait_group 1;"  ::: "memory")

__device__ __forceinline__ void ldsm4(uint32_t* r, uint32_t a) {
    asm volatile("ldmatrix.sync.aligned.m8n8.x4.shared.b16 {%0,%1,%2,%3}, [%4];"
        : "=r"(r[0]), "=r"(r[1]), "=r"(r[2]), "=r"(r[3]) : "r"(a));
}
__device__ __forceinline__ void ldsm4t(uint32_t* r, uint32_t a) {
    asm volatile("ldmatrix.sync.aligned.m8n8.x4.trans.shared.b16 {%0,%1,%2,%3}, [%4];"
        : "=r"(r[0]), "=r"(r[1]), "=r"(r[2]), "=r"(r[3]) : "r"(a));
}
__device__ __forceinline__ void mma16816(float* c, const uint32_t* a, const uint32_t* b) {
    asm volatile(
        "mma.sync.aligned.m16n8k16.row.col.f32.f16.f16.f32 "
        "{%0,%1,%2,%3}, {%4,%5,%6,%7}, {%8,%9}, {%0,%1,%2,%3};"
        : "+f"(c[0]), "+f"(c[1]), "+f"(c[2]), "+f"(c[3])
        : "r"(a[0]), "r"(a[1]), "r"(a[2]), "r"(a[3]), "r"(b[0]), "r"(b[1]));
}

// ---------------------------------------------------------------------------
// cvt5_kernel: fused fp32 -> fp16 over 5 regions (one launch).
// e0..e4 = exclusive region ends in float4 units (cumulative).
// ---------------------------------------------------------------------------
__global__ void cvt5_kernel(const float* __restrict__ s0, fp16* __restrict__ d0, int e0,
                            const float* __restrict__ s1, fp16* __restrict__ d1, int e1,
                            const float* __restrict__ s2, fp16* __restrict__ d2, int e2,
                            const float* __restrict__ s3, fp16* __restrict__ d3, int e3,
                            const float* __restrict__ s4, fp16* __restrict__ d4, int e4)
{
    int i = blockIdx.x * blockDim.x + threadIdx.x;
    if (i >= e4) return;
    const float* s; fp16* d; int base;
    if      (i < e0) { s = s0; d = d0; base = 0;  }
    else if (i < e1) { s = s1; d = d1; base = e0; }
    else if (i < e2) { s = s2; d = d2; base = e1; }
    else if (i < e3) { s = s3; d = d3; base = e2; }
    else             { s = s4; d = d4; base = e3; }
    int j = i - base;
    float4 v = __ldg((const float4*)s + j);
    fp162* D = (fp162*)d + 2 * j;
    D[0] = __floats2half2_rn(v.x, v.y);
    D[1] = __floats2half2_rn(v.z, v.w);
}

// ---------------------------------------------------------------------------
// fp16 HMMA GEMM, 512 threads (16 warps, 4x4 grid, 32x32 warp tile),
// 128x128 CTA tile, BK=64, 3-stage cp.async, register-double-buffered ldsm.
// MODE 0: fp32 out (+bias)
// MODE 1: relu(+bias) -> fp16 out (Ch)
// MODE 2: fp32 out = Rf + (+bias)
// MODE 3: fp16 out (+bias)
// SMEM per buffer: A 128x144B @0 (18432), B 64x272B @18432 (17408) = 35840 B
// ---------------------------------------------------------------------------
#define AST     144u
#define BST     272u
#define OFF_B   18432u
#define BUFSZ   35840u
#define NSTAGE  3
#define DSMEM   (NSTAGE * 35840)

template<int MODE>
__global__ __launch_bounds__(512)
void hgemm_kernel(const fp16* __restrict__ Ah, const fp16* __restrict__ Bh,
                  const float* __restrict__ bias,
                  const float* __restrict__ Rf,
                  float* __restrict__ Cf, fp16* __restrict__ Ch,
                  int N, int K)
{
    extern __shared__ char sm_[];
    const uint32_t sbase = smem_u32(sm_);

    const int tid  = threadIdx.x;
    const int wid  = tid >> 5;
    const int lane = tid & 31;
    const int wm   = (wid & 3) << 5;     // 0,32,64,96
    const int wn   = (wid >> 2) << 5;    // 0,32,64,96
    const int bm   = blockIdx.y << 7;
    const int bn   = blockIdx.x << 7;

    // loaders: A 128 rows x 8 segs of 16B; B 64 rows x 16 segs of 16B (2 iters)
    const int arow = tid >> 2, aseg = tid & 3;       // segs aseg, aseg+4
    const int brow = tid >> 4, bseg = tid & 15;      // rows brow, brow+32

    const fp16* Ap = Ah + (size_t)(bm + arow) * K + (aseg << 3);
    const fp16* Bp = Bh + (size_t)brow * N + bn + (bseg << 3);
    const uint32_t aDst  = (uint32_t)arow * AST + (uint32_t)(aseg << 4);
    const uint32_t bDst  = (uint32_t)brow * BST + (uint32_t)(bseg << 4);
    const size_t  bRow2  = (size_t)32 * N;
    const uint32_t bDst2 = bDst + 32u * BST;

    const int nchunk = K >> 6;

    float acc[2][4][4];
    #pragma unroll
    for (int i = 0; i < 2; i++)
        #pragma unroll
        for (int j = 0; j < 4; j++)
            #pragma unroll
            for (int k = 0; k < 4; k++) acc[i][j][k] = 0.f;

    // prologue: stages 0..NSTAGE-2
    #pragma unroll
    for (int s = 0; s < NSTAGE - 1; s++) {
        const uint32_t sb = sbase + (uint32_t)s * BUFSZ;
        cp16(sb + aDst,        Ap + (s << 6));
        cp16(sb + aDst + 64u,  Ap + (s << 6) + 32);
        cp16(sb + OFF_B + bDst,  Bp + (size_t)(s << 6) * N);
        cp16(sb + OFF_B + bDst2, Bp + bRow2 + (size_t)(s << 6) * N);
        CP_COMMIT();
    }

    const uint32_t aOffBase = (uint32_t)(wm + (lane & 15)) * AST
                            + (uint32_t)((lane >> 4) << 4);
    const uint32_t bOffBase = (uint32_t)(lane & 15) * BST
                            + (uint32_t)(wn << 1) + (uint32_t)((lane >> 4) << 4);

    #pragma unroll 1
    for (int c = 0; c < nchunk; c++) {
        CP_WAIT();
        __syncthreads();

        const uint32_t tb = sbase + (uint32_t)(c % NSTAGE) * BUFSZ;

        // register double-buffered operands
        uint32_t ra[2][2][4], rb[2][2][4];
        {
            const uint32_t aAd = tb + aOffBase;
            ldsm4(ra[0][0], aAd);
            ldsm4(ra[0][1], aAd + 16u * AST);
            const uint32_t bAd = tb + OFF_B + bOffBase;
            ldsm4t(rb[0][0], bAd);
            ldsm4t(rb[0][1], bAd + 32u);
        }

        #pragma unroll
        for (int ks = 0; ks < 4; ks++) {
            const int cur = ks & 1;
            const int nxt = cur ^ 1;
            if (ks < 3) {
                const uint32_t aAd = tb + aOffBase + (uint32_t)((ks + 1) << 5);
                ldsm4(ra[nxt][0], aAd);
                ldsm4(ra[nxt][1], aAd + 16u * AST);
                const uint32_t bAd = tb + OFF_B + bOffBase
                                   + (uint32_t)((ks + 1) << 4) * BST;
                ldsm4t(rb[nxt][0], bAd);
                ldsm4t(rb[nxt][1], bAd + 32u);
            }
            #pragma unroll
            for (int mt = 0; mt < 2; mt++)
                #pragma unroll
                for (int nt = 0; nt < 4; nt++)
                    mma16816(acc[mt][nt], ra[cur][mt],
                             &rb[cur][nt >> 1][(nt & 1) << 1]);
        }

        // issue stage c + NSTAGE-1
        const int cn = c + NSTAGE - 1;
        if (cn < nchunk) {
            const uint32_t nb = sbase + (uint32_t)(cn % NSTAGE) * BUFSZ;
            cp16(nb + aDst,        Ap + (cn << 6));
            cp16(nb + aDst + 64u,  Ap + (cn << 6) + 32);
            cp16(nb + OFF_B + bDst,  Bp + (size_t)(cn << 6) * N);
            cp16(nb + OFF_B + bDst2, Bp + bRow2 + (size_t)(cn << 6) * N);
        }
        CP_COMMIT();
    }

    // ---- epilogue ----
    #pragma unroll
    for (int mt = 0; mt < 2; mt++) {
        #pragma unroll
        for (int nt = 0; nt < 4; nt++) {
            const int m = bm + wm + (mt << 4) + (lane >> 2);
            const int n = bn + wn + (nt << 3) + ((lane & 3) << 1);
            const float b0 = __ldg(&bias[n]);
            const float b1 = __ldg(&bias[n + 1]);
            float2 v0, v1;
            v0.x = acc[mt][nt][0] + b0;  v0.y = acc[mt][nt][1] + b1;
            v1.x = acc[mt][nt][2] + b0;  v1.y = acc[mt][nt][3] + b1;
            const size_t i0 = (size_t)m * N + n;
            const size_t i1 = (size_t)(m + 8) * N + n;
            if (MODE == 0) {
                *(float2*)(Cf + i0) = v0;
                *(float2*)(Cf + i1) = v1;
            }
            if (MODE == 1) {
                v0.x = fmaxf(v0.x, 0.f); v0.y = fmaxf(v0.y, 0.f);
                v1.x = fmaxf(v1.x, 0.f); v1.y = fmaxf(v1.y, 0.f);
                *(fp162*)(Ch + i0) = __floats2half2_rn(v0.x, v0.y);
                *(fp162*)(Ch + i1) = __floats2half2_rn(v1.x, v1.y);
            }
            if (MODE == 2) {
                float2 r0 = *(const float2*)(Rf + i0);
                float2 r1 = *(const float2*)(Rf + i1);
                v0.x += r0.x; v0.y += r0.y;
                v1.x += r1.x; v1.y += r1.y;
                *(float2*)(Cf + i0) = v0;
                *(float2*)(Cf + i1) = v1;
            }
            if (MODE == 3) {
                *(fp162*)(Ch + i0) = __floats2half2_rn(v0.x, v0.y);
                *(fp162*)(Ch + i1) = __floats2half2_rn(v1.x, v1.y);
            }
        }
    }
}

// ---------------------------------------------------------------------------
// mpi_h = fp16(concat(memory, x))
// ---------------------------------------------------------------------------
__global__ void build_mpi_kernel(const float* __restrict__ mem,
                                 const float* __restrict__ x,
                                 fp16* __restrict__ hi)
{
    size_t i = (size_t)blockIdx.x * blockDim.x + threadIdx.x;  // pair index
    int    mp  = (int)(i & 511);
    size_t row = i >> 9;
    size_t b   = row / SP1_;
    int    s   = (int)(row - b * SP1_);
    const float* src = (s < S_) ? (mem + ((b * S_ + s) << 10)) : (x + (b << 10));
    float2 v = *(const float2*)(src + (mp << 1));
    ((fp162*)hi)[i] = __floats2half2_rn(v.x, v.y);
}

// ---------------------------------------------------------------------------
// gi[b,0:2] = x[b,:] @ kernel_gi + bias_gi
// ---------------------------------------------------------------------------
__global__ void gi_kernel(const float* __restrict__ x,
                          const float* __restrict__ kgi,
                          const float* __restrict__ bgi,
                          float* __restrict__ gi)
{
    int b    = blockIdx.x * 8 + (threadIdx.x >> 5);
    int lane = threadIdx.x & 31;
    const float* xr = x + (size_t)b * M_;
    float g0 = 0.f, g1 = 0.f;
    for (int m = lane; m < M_; m += 32) {
        float xv = xr[m];
        g0 = fmaf(xv, kgi[2 * m + 0], g0);
        g1 = fmaf(xv, kgi[2 * m + 1], g1);
    }
    #pragma unroll
    for (int o = 16; o; o >>= 1) {
        g0 += __shfl_xor_sync(0xffffffffu, g0, o);
        g1 += __shfl_xor_sync(0xffffffffu, g1, o);
    }
    if (lane == 0) {
        gi[2 * b + 0] = g0 + bgi[0];
        gi[2 * b + 1] = g1 + bgi[1];
    }
}

// ---------------------------------------------------------------------------
// Attention per (b,h): m1 = res + softmax(q k^T) v   (qkv in fp16)
// ---------------------------------------------------------------------------
__global__ __launch_bounds__(256)
void attn_kernel(const fp16* __restrict__ qkv,
                 const float* __restrict__ mem,
                 const float* __restrict__ x,
                 fp16* __restrict__ m1h, float* __restrict__ m1f)
{
    const int bh = blockIdx.x;
    const int b  = bh >> 3;
    const int h  = bh & 7;

    __shared__ float q [SP1_][128];
    __shared__ float kk[SP1_][128];
    __shared__ float vv[SP1_][128];
    __shared__ float sc[SP1_][SP1_];

    const float scale = rsqrtf((float)QKV_);
    const int tid = threadIdx.x;

    for (int i = tid; i < SP1_ * 64; i += 256) {
        int s = i >> 6, d = (i & 63) << 1;
        const fp16* base = qkv + ((size_t)(b * SP1_ + s)) * TOT_ + h * QKV_;
        fp162 qv = *(const fp162*)(base + d);
        fp162 kv = *(const fp162*)(base + 128 + d);
        fp162 vv2 = *(const fp162*)(base + 256 + d);
        q [s][d]     = __half2float(qv.x) * scale;
        q [s][d + 1] = __half2float(qv.y) * scale;
        kk[s][d]     = __half2float(kv.x);
        kk[s][d + 1] = __half2float(kv.y);
        vv[s][d]     = __half2float(vv2.x);
        vv[s][d + 1] = __half2float(vv2.y);
    }
    __syncthreads();

    const int w = tid >> 5, lane = tid & 31;
    for (int idx = w; idx < SP1_ * SP1_; idx += 8) {
        int i = idx / SP1_, j = idx - i * SP1_;
        float s = 0.f;
        for (int d = lane; d < 128; d += 32) s = fmaf(q[i][d], kk[j][d], s);
        #pragma unroll
        for (int o = 16; o; o >>= 1) s += __shfl_xor_sync(0xffffffffu, s, o);
        if (lane == 0) sc[i][j] = s;
    }
    __syncthreads();

    if (tid < SP1_) {
        float mx = -1e30f;
        #pragma unroll
        for (int j = 0; j < SP1_; j++) mx = fmaxf(mx, sc[tid][j]);
        float e[SP1_], sum = 0.f;
        #pragma unroll
        for (int j = 0; j < SP1_; j++) { e[j] = expf(sc[tid][j] - mx); sum += e[j]; }
        float inv = 1.f / sum;
        #pragma unroll
        for (int j = 0; j < SP1_; j++) sc[tid][j] = e[j] * inv;
    }
    __syncthreads();

    for (int i = tid; i < SP1_ * 64; i += 256) {
        int s  = i >> 6;
        int d  = (i & 63) << 1;
        float a0 = 0.f, a1 = 0.f;
        #pragma unroll
        for (int j = 0; j < SP1_; j++) {
            a0 = fmaf(sc[s][j], vv[j][d],     a0);
            a1 = fmaf(sc[s][j], vv[j][d + 1], a1);
        }
        const float* src = (s < S_) ? (mem + (((size_t)b * S_ + s) << 10))
                                    : (x + ((size_t)b << 10));
        float2 r = *(const float2*)(src + h * 128 + d);
        float v0 = r.x + a0;
        float v1 = r.y + a1;
        size_t o = ((size_t)(b * SP1_ + s)) * M_ + h * 128 + d;
        *(fp162*)(m1h + o) = __floats2half2_rn(v0, v1);
        *(float2*)(m1f + o) = make_float2(v0, v1);
    }
}

// ---------------------------------------------------------------------------
// Gate epilogue per (b,s)
// ---------------------------------------------------------------------------
__global__ __launch_bounds__(256)
void gate_kernel(const float* __restrict__ mem,
                 const float* __restrict__ m2,
                 const float* __restrict__ kgm,
                 const float* __restrict__ bgm,
                 const float* __restrict__ gi,
                 float* __restrict__ out)
{
    const int bs = blockIdx.x;
    const int b  = bs >> 3;
    const int s  = bs & 7;
    const int tid = threadIdx.x;

    const float* mrow  = mem + (size_t)bs * M_;
    const float* m2row = m2  + ((size_t)(b * SP1_ + s)) * M_;

    float g0 = 0.f, g1 = 0.f;
    for (int m = tid; m < M_; m += 256) {
        float t = tanhf(mrow[m]);
        g0 = fmaf(t, kgm[2 * m + 0], g0);
        g1 = fmaf(t, kgm[2 * m + 1], g1);
    }
    #pragma unroll
    for (int o = 16; o; o >>= 1) {
        g0 += __shfl_xor_sync(0xffffffffu, g0, o);
        g1 += __shfl_xor_sync(0xffffffffu, g1, o);
    }
    __shared__ float s0[8], s1[8];
    __shared__ float igs, fgs;
    int w = tid >> 5, lane = tid & 31;
    if (lane == 0) { s0[w] = g0; s1[w] = g1; }
    __syncthreads();
    if (tid == 0) {
        float G0 = 0.f, G1 = 0.f;
        #pragma unroll
        for (int i = 0; i < 8; i++) { G0 += s0[i]; G1 += s1[i]; }
        G0 += bgm[0] + gi[2 * b + 0];
        G1 += bgm[1] + gi[2 * b + 1] + 1.0f;
        igs = 1.f / (1.f + expf(-G0));
        fgs = 1.f / (1.f + expf(-G1));
    }
    __syncthreads();
    const float ig = igs, fg = fgs;

    float* orow = out + (size_t)b * (S_ * M_) + s * M_;
    for (int m = tid; m < M_; m += 256) {
        orow[m] = fmaf(ig, tanhf(m2row[m]), fg * mrow[m]);
    }
}

// ---------------------------------------------------------------------------
// kernel_launch
// ---------------------------------------------------------------------------
extern "C" void kernel_launch(void* const* d_in, const int* in_sizes, int n_in,
                              void* d_out, int out_size)
{
    const float* inputs   = (const float*)d_in[0];
    const float* memory   = (const float*)d_in[1];
    const float* k_qkv    = (const float*)d_in[2];
    const float* b_qkv    = (const float*)d_in[3];
    const float* k_gi     = (const float*)d_in[4];
    const float* b_gi     = (const float*)d_in[5];
    const float* k_gm     = (const float*)d_in[6];
    const float* b_gm     = (const float*)d_in[7];
    const float* k_in     = (const float*)d_in[8];
    const float* b_in     = (const float*)d_in[9];
    const float* mlp_k0   = (const float*)d_in[10];
    const float* mlp_b0   = (const float*)d_in[11];
    const float* mlp_k1   = (const float*)d_in[12];
    const float* mlp_b1   = (const float*)d_in[13];
    float* out = (float*)d_out;

    float *px, *pm1f, *pm2, *pgi;
    fp16 *pqkvh, *pinh, *pw, *pmpih, *pm1h, *phh;
    cudaGetSymbolAddress((void**)&px,    g_x);
    cudaGetSymbolAddress((void**)&pm1f,  g_m1f);
    cudaGetSymbolAddress((void**)&pm2,   g_m2);
    cudaGetSymbolAddress((void**)&pgi,   g_gi);
    cudaGetSymbolAddress((void**)&pqkvh, g_qkv_h);
    cudaGetSymbolAddress((void**)&pinh,  g_in_h);
    cudaGetSymbolAddress((void**)&pw,    g_w);
    cudaGetSymbolAddress((void**)&pmpih, g_mpi_h);
    cudaGetSymbolAddress((void**)&pm1h,  g_m1_h);
    cudaGetSymbolAddress((void**)&phh,   g_h_h);

    const size_t MM = (size_t)M_ * M_;
    fp16 *kinW = pw;
    fp16 *kqkW = pw + MM;
    fp16 *k0W  = pw + 4 * MM;
    fp16 *k1W  = pw + 5 * MM;

    cudaFuncSetAttribute(hgemm_kernel<0>, cudaFuncAttributeMaxDynamicSharedMemorySize, DSMEM);
    cudaFuncSetAttribute(hgemm_kernel<1>, cudaFuncAttributeMaxDynamicSharedMemorySize, DSMEM);
    cudaFuncSetAttribute(hgemm_kernel<2>, cudaFuncAttributeMaxDynamicSharedMemorySize, DSMEM);
    cudaFuncSetAttribute(hgemm_kernel<3>, cudaFuncAttributeMaxDynamicSharedMemorySize, DSMEM);

    // 0. fused conversion: inputs + 4 weight tensors (one launch)
    {
        const int n_in4  = B_ * M_ / 4;             // 524288
        const int n_1M4  = (int)(MM / 4);           // 262144
        const int n_3M4  = (int)(3 * MM / 4);       // 786432
        const int e0 = n_in4;
        const int e1 = e0 + n_1M4;
        const int e2 = e1 + n_3M4;
        const int e3 = e2 + n_1M4;
        const int e4 = e3 + n_1M4;
        cvt5_kernel<<<(e4 + 255) / 256, 256>>>(
            inputs, pinh, e0,
            k_in,   kinW, e1,
            k_qkv,  kqkW, e2,
            mlp_k0, k0W,  e3,
            mlp_k1, k1W,  e4);
    }

    // 1. x = inputs @ kernel_in + bias_in   (fp32 out — feeds gi + residuals)
    hgemm_kernel<0><<<dim3(M_ / 128, B_ / 128), 512, DSMEM>>>(
        pinh, kinW, b_in, nullptr, px, nullptr, M_, M_);

    // 2. mpi (fp16)
    build_mpi_kernel<<<(unsigned)(((size_t)ROWS_ * M_ / 2) / 256), 256>>>(
        memory, px, pmpih);

    // 3. gi
    gi_kernel<<<B_ / 8, 256>>>(px, k_gi, b_gi, pgi);

    // 4. qkv = mpi @ kernel_qkv + bias_qkv   (fp16 out)
    hgemm_kernel<3><<<dim3(TOT_ / 128, ROWS_ / 128), 512, DSMEM>>>(
        pmpih, kqkW, b_qkv, nullptr, nullptr, pqkvh, TOT_, M_);

    // 5. attention + fp32 residual -> m1 (fp16 + fp32)
    attn_kernel<<<B_ * H_, 256>>>(pqkvh, memory, px, pm1h, pm1f);

    // 6. h = relu(m1 @ mlp_k0 + mlp_b0) -> fp16
    hgemm_kernel<1><<<dim3(M_ / 128, ROWS_ / 128), 512, DSMEM>>>(
        pm1h, k0W, mlp_b0, nullptr, nullptr, phh, M_, M_);

    // 7. m2 = m1(fp32) + h @ mlp_k1 + mlp_b1
    hgemm_kernel<2><<<dim3(M_ / 128, ROWS_ / 128), 512, DSMEM>>>(
        phh, k1W, mlp_b1, pm1f, pm2, nullptr, M_, M_);

    // 8. gates + output
    gate_kernel<<<B_ * S_, 256>>>(memory, pm2, k_gm, b_gm, pgi, out);
}

// round 13
// speedup vs baseline: 1.1731x; 1.0628x over previous
#include <cuda_runtime.h>
#include <cuda_fp16.h>
#include <math.h>
#include <stdint.h>

// ---------------------------------------------------------------------------
// RelationalMemoryCell  (B=2048, S=8, H=8, M=1024, QKV=384, TOT=3072)
// Round 13: R10 GEMM core (at mma.sync HW ceiling) +
//   (1) MLP GEMMs on compacted 16384 rows (drop discarded s==8 row)
//   (2) gate epilogue fused into final GEMM (MODE 4), m2 eliminated.
// ---------------------------------------------------------------------------

#define B_     2048
#define S_     8
#define H_     8
#define M_     1024
#define QKV_   384
#define TOT_   3072
#define SP1_   9
#define ROWS_  (B_*SP1_)   // 18432
#define CROWS_ (B_*S_)     // 16384 (compacted: s<8 only)

typedef __half  fp16;
typedef __half2 fp162;

// ---- global scratch (allocation-free rule) ----
__device__ __align__(256) float g_x    [(size_t)B_    * M_];
__device__ __align__(256) float g_m1f  [(size_t)CROWS_* M_];
__device__ __align__(256) float g_gi   [(size_t)B_ * 2];
__device__ __align__(256) float g_gates[(size_t)CROWS_ * 2];

__device__ __align__(256) fp16 g_qkv_h [(size_t)ROWS_ * TOT_];
__device__ __align__(256) fp16 g_in_h  [(size_t)B_ * M_];
// weights arena (fp16): k_in @0 (1M), k_qkv @1M (3M), mlp_k0 @4M, mlp_k1 @5M
__device__ __align__(256) fp16 g_w     [(size_t)6 * M_ * M_];
__device__ __align__(256) fp16 g_mpi_h [(size_t)ROWS_ * M_];
__device__ __align__(256) fp16 g_m1_h  [(size_t)CROWS_ * M_];
__device__ __align__(256) fp16 g_h_h   [(size_t)CROWS_ * M_];

// ---------------------------------------------------------------------------
// helpers
// ---------------------------------------------------------------------------
__device__ __forceinline__ uint32_t smem_u32(const void* p) {
    uint32_t a;
    asm("{ .reg .u64 t; cvta.to.shared.u64 t, %1; cvt.u32.u64 %0, t; }"
        : "=r"(a) : "l"(p));
    return a;
}
__device__ __forceinline__ void cp16(uint32_t dst, const void* src) {
    asm volatile("cp.async.cg.shared.global [%0], [%1], 16;"
                 :: "r"(dst), "l"(src) : "memory");
}
#define CP_COMMIT() asm volatile("cp.async.commit_group;" ::: "memory")
#define CP_WAIT()   asm volatile("cp.async.wait_group 1;"  ::: "memory")

__device__ __forceinline__ void ldsm4(uint32_t* r, uint32_t a) {
    asm volatile("ldmatrix.sync.aligned.m8n8.x4.shared.b16 {%0,%1,%2,%3}, [%4];"
        : "=r"(r[0]), "=r"(r[1]), "=r"(r[2]), "=r"(r[3]) : "r"(a));
}
__device__ __forceinline__ void ldsm4t(uint32_t* r, uint32_t a) {
    asm volatile("ldmatrix.sync.aligned.m8n8.x4.trans.shared.b16 {%0,%1,%2,%3}, [%4];"
        : "=r"(r[0]), "=r"(r[1]), "=r"(r[2]), "=r"(r[3]) : "r"(a));
}
__device__ __forceinline__ void mma16816(float* c, const uint32_t* a, const uint32_t* b) {
    asm volatile(
        "mma.sync.aligned.m16n8k16.row.col.f32.f16.f16.f32 "
        "{%0,%1,%2,%3}, {%4,%5,%6,%7}, {%8,%9}, {%0,%1,%2,%3};"
        : "+f"(c[0]), "+f"(c[1]), "+f"(c[2]), "+f"(c[3])
        : "r"(a[0]), "r"(a[1]), "r"(a[2]), "r"(a[3]), "r"(b[0]), "r"(b[1]));
}

// ---------------------------------------------------------------------------
// cvt5_kernel: fused fp32 -> fp16 over 5 regions (one launch).
// ---------------------------------------------------------------------------
__global__ void cvt5_kernel(const float* __restrict__ s0, fp16* __restrict__ d0, int e0,
                            const float* __restrict__ s1, fp16* __restrict__ d1, int e1,
                            const float* __restrict__ s2, fp16* __restrict__ d2, int e2,
                            const float* __restrict__ s3, fp16* __restrict__ d3, int e3,
                            const float* __restrict__ s4, fp16* __restrict__ d4, int e4)
{
    int i = blockIdx.x * blockDim.x + threadIdx.x;
    if (i >= e4) return;
    const float* s; fp16* d; int base;
    if      (i < e0) { s = s0; d = d0; base = 0;  }
    else if (i < e1) { s = s1; d = d1; base = e0; }
    else if (i < e2) { s = s2; d = d2; base = e1; }
    else if (i < e3) { s = s3; d = d3; base = e2; }
    else             { s = s4; d = d4; base = e3; }
    int j = i - base;
    float4 v = __ldg((const float4*)s + j);
    fp162* D = (fp162*)d + 2 * j;
    D[0] = __floats2half2_rn(v.x, v.y);
    D[1] = __floats2half2_rn(v.z, v.w);
}

// ---------------------------------------------------------------------------
// fp16 HMMA GEMM, 512 threads (16 warps, 4x4 grid, 32x32 warp tile),
// 128x128 CTA tile, BK=64, 3-stage cp.async (R10 inner loop).
// MODE 0: fp32 out (+bias)
// MODE 1: relu(+bias) -> fp16 out (Ch)
// MODE 3: fp16 out (+bias)
// MODE 4: gated output: v = Rf + (.+bias); Cf = ig*tanh(v) + fg*mem
// ---------------------------------------------------------------------------
#define AST     144u
#define BST     272u
#define OFF_B   18432u
#define BUFSZ   35840u
#define NSTAGE  3
#define DSMEM   (NSTAGE * 35840)

template<int MODE>
__global__ __launch_bounds__(512)
void hgemm_kernel(const fp16* __restrict__ Ah, const fp16* __restrict__ Bh,
                  const float* __restrict__ bias,
                  const float* __restrict__ Rf,
                  const float* __restrict__ Gmem,   // mem rows (MODE 4)
                  const float* __restrict__ Gates,  // [row*2] ig, fg (MODE 4)
                  float* __restrict__ Cf, fp16* __restrict__ Ch,
                  int N, int K)
{
    extern __shared__ char sm_[];
    const uint32_t sbase = smem_u32(sm_);

    const int tid  = threadIdx.x;
    const int wid  = tid >> 5;
    const int lane = tid & 31;
    const int wm   = (wid & 3) << 5;
    const int wn   = (wid >> 2) << 5;
    const int bm   = blockIdx.y << 7;
    const int bn   = blockIdx.x << 7;

    const int arow = tid >> 2, aseg = tid & 3;       // A segs aseg, aseg+4
    const int brow = tid >> 4, bseg = tid & 15;      // B rows brow, brow+32

    const fp16* Ap = Ah + (size_t)(bm + arow) * K + (aseg << 3);
    const fp16* Bp = Bh + (size_t)brow * N + bn + (bseg << 3);
    const uint32_t aDst  = (uint32_t)arow * AST + (uint32_t)(aseg << 4);
    const uint32_t bDst  = (uint32_t)brow * BST + (uint32_t)(bseg << 4);
    const size_t  bRow2  = (size_t)32 * N;
    const uint32_t bDst2 = bDst + 32u * BST;

    const int nchunk = K >> 6;

    float acc[2][4][4];
    #pragma unroll
    for (int i = 0; i < 2; i++)
        #pragma unroll
        for (int j = 0; j < 4; j++)
            #pragma unroll
            for (int k = 0; k < 4; k++) acc[i][j][k] = 0.f;

    #pragma unroll
    for (int s = 0; s < NSTAGE - 1; s++) {
        const uint32_t sb = sbase + (uint32_t)s * BUFSZ;
        cp16(sb + aDst,        Ap + (s << 6));
        cp16(sb + aDst + 64u,  Ap + (s << 6) + 32);
        cp16(sb + OFF_B + bDst,  Bp + (size_t)(s << 6) * N);
        cp16(sb + OFF_B + bDst2, Bp + bRow2 + (size_t)(s << 6) * N);
        CP_COMMIT();
    }

    const uint32_t aOffBase = (uint32_t)(wm + (lane & 15)) * AST
                            + (uint32_t)((lane >> 4) << 4);
    const uint32_t bOffBase = (uint32_t)(lane & 15) * BST
                            + (uint32_t)(wn << 1) + (uint32_t)((lane >> 4) << 4);

    #pragma unroll 1
    for (int c = 0; c < nchunk; c++) {
        CP_WAIT();
        __syncthreads();

        const uint32_t tb = sbase + (uint32_t)(c % NSTAGE) * BUFSZ;

        #pragma unroll
        for (int ks = 0; ks < 4; ks++) {
            uint32_t ra[2][4], rb[2][4];
            const uint32_t aAd = tb + aOffBase + (uint32_t)(ks << 5);
            ldsm4(ra[0], aAd);
            ldsm4(ra[1], aAd + 16u * AST);
            const uint32_t bAd = tb + OFF_B + bOffBase + (uint32_t)(ks << 4) * BST;
            ldsm4t(rb[0], bAd);
            ldsm4t(rb[1], bAd + 32u);
            #pragma unroll
            for (int mt = 0; mt < 2; mt++)
                #pragma unroll
                for (int nt = 0; nt < 4; nt++)
                    mma16816(acc[mt][nt], ra[mt], &rb[nt >> 1][(nt & 1) << 1]);
        }

        const int cn = c + NSTAGE - 1;
        if (cn < nchunk) {
            const uint32_t nb = sbase + (uint32_t)(cn % NSTAGE) * BUFSZ;
            cp16(nb + aDst,        Ap + (cn << 6));
            cp16(nb + aDst + 64u,  Ap + (cn << 6) + 32);
            cp16(nb + OFF_B + bDst,  Bp + (size_t)(cn << 6) * N);
            cp16(nb + OFF_B + bDst2, Bp + bRow2 + (size_t)(cn << 6) * N);
        }
        CP_COMMIT();
    }

    // ---- epilogue ----
    #pragma unroll
    for (int mt = 0; mt < 2; mt++) {
        float ig0 = 0.f, fg0 = 0.f, ig1 = 0.f, fg1 = 0.f;
        if (MODE == 4) {
            const int mA = bm + wm + (mt << 4) + (lane >> 2);
            float2 gA = *(const float2*)(Gates + 2 * mA);
            float2 gB = *(const float2*)(Gates + 2 * (mA + 8));
            ig0 = gA.x; fg0 = gA.y;
            ig1 = gB.x; fg1 = gB.y;
        }
        #pragma unroll
        for (int nt = 0; nt < 4; nt++) {
            const int m = bm + wm + (mt << 4) + (lane >> 2);
            const int n = bn + wn + (nt << 3) + ((lane & 3) << 1);
            const float b0 = __ldg(&bias[n]);
            const float b1 = __ldg(&bias[n + 1]);
            float2 v0, v1;
            v0.x = acc[mt][nt][0] + b0;  v0.y = acc[mt][nt][1] + b1;
            v1.x = acc[mt][nt][2] + b0;  v1.y = acc[mt][nt][3] + b1;
            const size_t i0 = (size_t)m * N + n;
            const size_t i1 = (size_t)(m + 8) * N + n;
            if (MODE == 0) {
                *(float2*)(Cf + i0) = v0;
                *(float2*)(Cf + i1) = v1;
            }
            if (MODE == 1) {
                v0.x = fmaxf(v0.x, 0.f); v0.y = fmaxf(v0.y, 0.f);
                v1.x = fmaxf(v1.x, 0.f); v1.y = fmaxf(v1.y, 0.f);
                *(fp162*)(Ch + i0) = __floats2half2_rn(v0.x, v0.y);
                *(fp162*)(Ch + i1) = __floats2half2_rn(v1.x, v1.y);
            }
            if (MODE == 3) {
                *(fp162*)(Ch + i0) = __floats2half2_rn(v0.x, v0.y);
                *(fp162*)(Ch + i1) = __floats2half2_rn(v1.x, v1.y);
            }
            if (MODE == 4) {
                float2 r0 = *(const float2*)(Rf + i0);
                float2 r1 = *(const float2*)(Rf + i1);
                float2 w0 = *(const float2*)(Gmem + i0);
                float2 w1 = *(const float2*)(Gmem + i1);
                float2 o0, o1;
                o0.x = fmaf(ig0, tanhf(v0.x + r0.x), fg0 * w0.x);
                o0.y = fmaf(ig0, tanhf(v0.y + r0.y), fg0 * w0.y);
                o1.x = fmaf(ig1, tanhf(v1.x + r1.x), fg1 * w1.x);
                o1.y = fmaf(ig1, tanhf(v1.y + r1.y), fg1 * w1.y);
                *(float2*)(Cf + i0) = o0;
                *(float2*)(Cf + i1) = o1;
            }
        }
    }
}

// ---------------------------------------------------------------------------
// mpi_h = fp16(concat(memory, x))  (all 9 rows — qkv GEMM input)
// ---------------------------------------------------------------------------
__global__ void build_mpi_kernel(const float* __restrict__ mem,
                                 const float* __restrict__ x,
                                 fp16* __restrict__ hi)
{
    size_t i = (size_t)blockIdx.x * blockDim.x + threadIdx.x;  // pair index
    int    mp  = (int)(i & 511);
    size_t row = i >> 9;
    size_t b   = row / SP1_;
    int    s   = (int)(row - b * SP1_);
    const float* src = (s < S_) ? (mem + ((b * S_ + s) << 10)) : (x + (b << 10));
    float2 v = *(const float2*)(src + (mp << 1));
    ((fp162*)hi)[i] = __floats2half2_rn(v.x, v.y);
}

// ---------------------------------------------------------------------------
// gi[b,0:2] = x[b,:] @ kernel_gi + bias_gi
// ---------------------------------------------------------------------------
__global__ void gi_kernel(const float* __restrict__ x,
                          const float* __restrict__ kgi,
                          const float* __restrict__ bgi,
                          float* __restrict__ gi)
{
    int b    = blockIdx.x * 8 + (threadIdx.x >> 5);
    int lane = threadIdx.x & 31;
    const float* xr = x + (size_t)b * M_;
    float g0 = 0.f, g1 = 0.f;
    for (int m = lane; m < M_; m += 32) {
        float xv = xr[m];
        g0 = fmaf(xv, kgi[2 * m + 0], g0);
        g1 = fmaf(xv, kgi[2 * m + 1], g1);
    }
    #pragma unroll
    for (int o = 16; o; o >>= 1) {
        g0 += __shfl_xor_sync(0xffffffffu, g0, o);
        g1 += __shfl_xor_sync(0xffffffffu, g1, o);
    }
    if (lane == 0) {
        gi[2 * b + 0] = g0 + bgi[0];
        gi[2 * b + 1] = g1 + bgi[1];
    }
}

// ---------------------------------------------------------------------------
// gates_kernel per (b,s): gm = tanh(mem row) @ kgm; gates -> sigmoid
// writes g_gates[2*bs] = input_gate, [2*bs+1] = forget_gate
// ---------------------------------------------------------------------------
__global__ __launch_bounds__(256)
void gates_kernel(const float* __restrict__ mem,
                  const float* __restrict__ kgm,
                  const float* __restrict__ bgm,
                  const float* __restrict__ gi,
                  float* __restrict__ gates)
{
    const int bs = blockIdx.x;      // b*8 + s
    const int b  = bs >> 3;
    const int tid = threadIdx.x;

    const float* mrow = mem + (size_t)bs * M_;

    float g0 = 0.f, g1 = 0.f;
    for (int m = tid; m < M_; m += 256) {
        float t = tanhf(mrow[m]);
        g0 = fmaf(t, kgm[2 * m + 0], g0);
        g1 = fmaf(t, kgm[2 * m + 1], g1);
    }
    #pragma unroll
    for (int o = 16; o; o >>= 1) {
        g0 += __shfl_xor_sync(0xffffffffu, g0, o);
        g1 += __shfl_xor_sync(0xffffffffu, g1, o);
    }
    __shared__ float s0[8], s1[8];
    int w = tid >> 5, lane = tid & 31;
    if (lane == 0) { s0[w] = g0; s1[w] = g1; }
    __syncthreads();
    if (tid == 0) {
        float G0 = 0.f, G1 = 0.f;
        #pragma unroll
        for (int i = 0; i < 8; i++) { G0 += s0[i]; G1 += s1[i]; }
        G0 += bgm[0] + gi[2 * b + 0];
        G1 += bgm[1] + gi[2 * b + 1] + 1.0f;
        gates[2 * bs + 0] = 1.f / (1.f + expf(-G0));
        gates[2 * bs + 1] = 1.f / (1.f + expf(-G1));
    }
}

// ---------------------------------------------------------------------------
// Attention per (b,h): m1 = res + softmax(q k^T) v
// writes COMPACTED m1 (rows b*8+s, s<8 only)
// ---------------------------------------------------------------------------
__global__ __launch_bounds__(256)
void attn_kernel(const fp16* __restrict__ qkv,
                 const float* __restrict__ mem,
                 const float* __restrict__ x,
                 fp16* __restrict__ m1h, float* __restrict__ m1f)
{
    const int bh = blockIdx.x;
    const int b  = bh >> 3;
    const int h  = bh & 7;

    __shared__ float q [SP1_][128];
    __shared__ float kk[SP1_][128];
    __shared__ float vv[SP1_][128];
    __shared__ float sc[SP1_][SP1_];

    const float scale = rsqrtf((float)QKV_);
    const int tid = threadIdx.x;

    for (int i = tid; i < SP1_ * 64; i += 256) {
        int s = i >> 6, d = (i & 63) << 1;
        const fp16* base = qkv + ((size_t)(b * SP1_ + s)) * TOT_ + h * QKV_;
        fp162 qv  = *(const fp162*)(base + d);
        fp162 kv  = *(const fp162*)(base + 128 + d);
        fp162 vv2 = *(const fp162*)(base + 256 + d);
        q [s][d]     = __half2float(qv.x) * scale;
        q [s][d + 1] = __half2float(qv.y) * scale;
        kk[s][d]     = __half2float(kv.x);
        kk[s][d + 1] = __half2float(kv.y);
        vv[s][d]     = __half2float(vv2.x);
        vv[s][d + 1] = __half2float(vv2.y);
    }
    __syncthreads();

    const int w = tid >> 5, lane = tid & 31;
    for (int idx = w; idx < SP1_ * SP1_; idx += 8) {
        int i = idx / SP1_, j = idx - i * SP1_;
        float s = 0.f;
        for (int d = lane; d < 128; d += 32) s = fmaf(q[i][d], kk[j][d], s);
        #pragma unroll
        for (int o = 16; o; o >>= 1) s += __shfl_xor_sync(0xffffffffu, s, o);
        if (lane == 0) sc[i][j] = s;
    }
    __syncthreads();

    // softmax only needed for query rows s<8 (row 8 discarded), but compute
    // all 9 — cheap and keeps code simple
    if (tid < SP1_) {
        float mx = -1e30f;
        #pragma unroll
        for (int j = 0; j < SP1_; j++) mx = fmaxf(mx, sc[tid][j]);
        float e[SP1_], sum = 0.f;
        #pragma unroll
        for (int j = 0; j < SP1_; j++) { e[j] = expf(sc[tid][j] - mx); sum += e[j]; }
        float inv = 1.f / sum;
        #pragma unroll
        for (int j = 0; j < SP1_; j++) sc[tid][j] = e[j] * inv;
    }
    __syncthreads();

    // only s<8 rows stored (compacted)
    for (int i = tid; i < S_ * 64; i += 256) {
        int s  = i >> 6;
        int d  = (i & 63) << 1;
        float a0 = 0.f, a1 = 0.f;
        #pragma unroll
        for (int j = 0; j < SP1_; j++) {
            a0 = fmaf(sc[s][j], vv[j][d],     a0);
            a1 = fmaf(sc[s][j], vv[j][d + 1], a1);
        }
        const float* src = mem + (((size_t)b * S_ + s) << 10);
        float2 r = *(const float2*)(src + h * 128 + d);
        float v0 = r.x + a0;
        float v1 = r.y + a1;
        size_t o = ((size_t)(b * S_ + s)) * M_ + h * 128 + d;
        *(fp162*)(m1h + o) = __floats2half2_rn(v0, v1);
        *(float2*)(m1f + o) = make_float2(v0, v1);
    }
}

// ---------------------------------------------------------------------------
// kernel_launch
// ---------------------------------------------------------------------------
extern "C" void kernel_launch(void* const* d_in, const int* in_sizes, int n_in,
                              void* d_out, int out_size)
{
    const float* inputs   = (const float*)d_in[0];
    const float* memory   = (const float*)d_in[1];
    const float* k_qkv    = (const float*)d_in[2];
    const float* b_qkv    = (const float*)d_in[3];
    const float* k_gi     = (const float*)d_in[4];
    const float* b_gi     = (const float*)d_in[5];
    const float* k_gm     = (const float*)d_in[6];
    const float* b_gm     = (const float*)d_in[7];
    const float* k_in     = (const float*)d_in[8];
    const float* b_in     = (const float*)d_in[9];
    const float* mlp_k0   = (const float*)d_in[10];
    const float* mlp_b0   = (const float*)d_in[11];
    const float* mlp_k1   = (const float*)d_in[12];
    const float* mlp_b1   = (const float*)d_in[13];
    float* out = (float*)d_out;

    float *px, *pm1f, *pgi, *pgates;
    fp16 *pqkvh, *pinh, *pw, *pmpih, *pm1h, *phh;
    cudaGetSymbolAddress((void**)&px,     g_x);
    cudaGetSymbolAddress((void**)&pm1f,   g_m1f);
    cudaGetSymbolAddress((void**)&pgi,    g_gi);
    cudaGetSymbolAddress((void**)&pgates, g_gates);
    cudaGetSymbolAddress((void**)&pqkvh,  g_qkv_h);
    cudaGetSymbolAddress((void**)&pinh,   g_in_h);
    cudaGetSymbolAddress((void**)&pw,     g_w);
    cudaGetSymbolAddress((void**)&pmpih,  g_mpi_h);
    cudaGetSymbolAddress((void**)&pm1h,   g_m1_h);
    cudaGetSymbolAddress((void**)&phh,    g_h_h);

    const size_t MM = (size_t)M_ * M_;
    fp16 *kinW = pw;
    fp16 *kqkW = pw + MM;
    fp16 *k0W  = pw + 4 * MM;
    fp16 *k1W  = pw + 5 * MM;

    cudaFuncSetAttribute(hgemm_kernel<0>, cudaFuncAttributeMaxDynamicSharedMemorySize, DSMEM);
    cudaFuncSetAttribute(hgemm_kernel<1>, cudaFuncAttributeMaxDynamicSharedMemorySize, DSMEM);
    cudaFuncSetAttribute(hgemm_kernel<3>, cudaFuncAttributeMaxDynamicSharedMemorySize, DSMEM);
    cudaFuncSetAttribute(hgemm_kernel<4>, cudaFuncAttributeMaxDynamicSharedMemorySize, DSMEM);

    // 0. fused conversion: inputs + 4 weight tensors (one launch)
    {
        const int n_in4  = B_ * M_ / 4;
        const int n_1M4  = (int)(MM / 4);
        const int n_3M4  = (int)(3 * MM / 4);
        const int e0 = n_in4;
        const int e1 = e0 + n_1M4;
        const int e2 = e1 + n_3M4;
        const int e3 = e2 + n_1M4;
        const int e4 = e3 + n_1M4;
        cvt5_kernel<<<(e4 + 255) / 256, 256>>>(
            inputs, pinh, e0,
            k_in,   kinW, e1,
            k_qkv,  kqkW, e2,
            mlp_k0, k0W,  e3,
            mlp_k1, k1W,  e4);
    }

    // 1. x = inputs @ kernel_in + bias_in   (fp32 out)
    hgemm_kernel<0><<<dim3(M_ / 128, B_ / 128), 512, DSMEM>>>(
        pinh, kinW, b_in, nullptr, nullptr, nullptr, px, nullptr, M_, M_);

    // 2. mpi (fp16, 9 rows)
    build_mpi_kernel<<<(unsigned)(((size_t)ROWS_ * M_ / 2) / 256), 256>>>(
        memory, px, pmpih);

    // 3. gi + gates
    gi_kernel<<<B_ / 8, 256>>>(px, k_gi, b_gi, pgi);
    gates_kernel<<<CROWS_, 256>>>(memory, k_gm, b_gm, pgi, pgates);

    // 4. qkv = mpi @ kernel_qkv + bias_qkv   (fp16 out)
    hgemm_kernel<3><<<dim3(TOT_ / 128, ROWS_ / 128), 512, DSMEM>>>(
        pmpih, kqkW, b_qkv, nullptr, nullptr, nullptr, nullptr, pqkvh, TOT_, M_);

    // 5. attention + fp32 residual -> compacted m1 (fp16 + fp32, 16384 rows)
    attn_kernel<<<B_ * H_, 256>>>(pqkvh, memory, px, pm1h, pm1f);

    // 6. h = relu(m1 @ mlp_k0 + mlp_b0) -> fp16   (16384 rows)
    hgemm_kernel<1><<<dim3(M_ / 128, CROWS_ / 128), 512, DSMEM>>>(
        pm1h, k0W, mlp_b0, nullptr, nullptr, nullptr, nullptr, phh, M_, M_);

    // 7. out = ig*tanh(m1 + h @ mlp_k1 + mlp_b1) + fg*mem   (fused gate)
    hgemm_kernel<4><<<dim3(M_ / 128, CROWS_ / 128), 512, DSMEM>>>(
        phh, k1W, mlp_b1, pm1f, memory, pgates, out, nullptr, M_, M_);
}

// round 14
// speedup vs baseline: 1.1782x; 1.0043x over previous
#include <cuda_runtime.h>
#include <cuda_fp16.h>
#include <math.h>
#include <stdint.h>

// ---------------------------------------------------------------------------
// RelationalMemoryCell  (B=2048, S=8, H=8, M=1024, QKV=384, TOT=3072)
// Round 14: R13 + build_mpi eliminated (cvt6 strided region + GEMM-1 MODE 5
// epilogue writes mpi row s==8) + gi occupancy fix.
// ---------------------------------------------------------------------------

#define B_     2048
#define S_     8
#define H_     8
#define M_     1024
#define QKV_   384
#define TOT_   3072
#define SP1_   9
#define ROWS_  (B_*SP1_)   // 18432
#define CROWS_ (B_*S_)     // 16384

typedef __half  fp16;
typedef __half2 fp162;

// ---- global scratch (allocation-free rule) ----
__device__ __align__(256) float g_x    [(size_t)B_    * M_];
__device__ __align__(256) float g_m1f  [(size_t)CROWS_* M_];
__device__ __align__(256) float g_gi   [(size_t)B_ * 2];
__device__ __align__(256) float g_gates[(size_t)CROWS_ * 2];

__device__ __align__(256) fp16 g_qkv_h [(size_t)ROWS_ * TOT_];
__device__ __align__(256) fp16 g_in_h  [(size_t)B_ * M_];
__device__ __align__(256) fp16 g_w     [(size_t)6 * M_ * M_];
__device__ __align__(256) fp16 g_mpi_h [(size_t)ROWS_ * M_];
__device__ __align__(256) fp16 g_m1_h  [(size_t)CROWS_ * M_];
__device__ __align__(256) fp16 g_h_h   [(size_t)CROWS_ * M_];

// ---------------------------------------------------------------------------
// helpers
// ---------------------------------------------------------------------------
__device__ __forceinline__ uint32_t smem_u32(const void* p) {
    uint32_t a;
    asm("{ .reg .u64 t; cvta.to.shared.u64 t, %1; cvt.u32.u64 %0, t; }"
        : "=r"(a) : "l"(p));
    return a;
}
__device__ __forceinline__ void cp16(uint32_t dst, const void* src) {
    asm volatile("cp.async.cg.shared.global [%0], [%1], 16;"
                 :: "r"(dst), "l"(src) : "memory");
}
#define CP_COMMIT() asm volatile("cp.async.commit_group;" ::: "memory")
#define CP_WAIT()   asm volatile("cp.async.wait_group 1;"  ::: "memory")

__device__ __forceinline__ void ldsm4(uint32_t* r, uint32_t a) {
    asm volatile("ldmatrix.sync.aligned.m8n8.x4.shared.b16 {%0,%1,%2,%3}, [%4];"
        : "=r"(r[0]), "=r"(r[1]), "=r"(r[2]), "=r"(r[3]) : "r"(a));
}
__device__ __forceinline__ void ldsm4t(uint32_t* r, uint32_t a) {
    asm volatile("ldmatrix.sync.aligned.m8n8.x4.trans.shared.b16 {%0,%1,%2,%3}, [%4];"
        : "=r"(r[0]), "=r"(r[1]), "=r"(r[2]), "=r"(r[3]) : "r"(a));
}
__device__ __forceinline__ void mma16816(float* c, const uint32_t* a, const uint32_t* b) {
    asm volatile(
        "mma.sync.aligned.m16n8k16.row.col.f32.f16.f16.f32 "
        "{%0,%1,%2,%3}, {%4,%5,%6,%7}, {%8,%9}, {%0,%1,%2,%3};"
        : "+f"(c[0]), "+f"(c[1]), "+f"(c[2]), "+f"(c[3])
        : "r"(a[0]), "r"(a[1]), "r"(a[2]), "r"(a[3]), "r"(b[0]), "r"(b[1]));
}

// ---------------------------------------------------------------------------
// cvt6_kernel: fused fp32 -> fp16.  Regions 0..4 contiguous (inputs + 4
// weights).  Region 5 = memory -> mpi rows (strided dst: row b*8+s maps to
// mpi row b*9+s).
// ---------------------------------------------------------------------------
__global__ void cvt6_kernel(const float* __restrict__ s0, fp16* __restrict__ d0, int e0,
                            const float* __restrict__ s1, fp16* __restrict__ d1, int e1,
                            const float* __restrict__ s2, fp16* __restrict__ d2, int e2,
                            const float* __restrict__ s3, fp16* __restrict__ d3, int e3,
                            const float* __restrict__ s4, fp16* __restrict__ d4, int e4,
                            const float* __restrict__ mem, fp16* __restrict__ mpi, int e5)
{
    int i = blockIdx.x * blockDim.x + threadIdx.x;
    if (i >= e5) return;
    if (i >= e4) {
        // memory region: j-th float4 of memory (CROWS_ x M_)
        int j = i - e4;
        float4 v = __ldg((const float4*)mem + j);
        int row    = j >> 8;              // (j*4) / 1024
        int within = (j & 255) << 1;      // pair index within row
        int b = row >> 3, s = row & 7;
        fp162* D = (fp162*)mpi + (((size_t)(b * SP1_ + s)) << 9) + within;
        D[0] = __floats2half2_rn(v.x, v.y);
        D[1] = __floats2half2_rn(v.z, v.w);
        return;
    }
    const float* s; fp16* d; int base;
    if      (i < e0) { s = s0; d = d0; base = 0;  }
    else if (i < e1) { s = s1; d = d1; base = e0; }
    else if (i < e2) { s = s2; d = d2; base = e1; }
    else if (i < e3) { s = s3; d = d3; base = e2; }
    else             { s = s4; d = d4; base = e3; }
    int j = i - base;
    float4 v = __ldg((const float4*)s + j);
    fp162* D = (fp162*)d + 2 * j;
    D[0] = __floats2half2_rn(v.x, v.y);
    D[1] = __floats2half2_rn(v.z, v.w);
}

// ---------------------------------------------------------------------------
// fp16 HMMA GEMM, 512 threads (16 warps, 4x4, 32x32 warp tile),
// 128x128 CTA tile, BK=64, 3-stage cp.async (R10 inner loop).
// MODE 1: relu(+bias) -> fp16 out (Ch)
// MODE 3: fp16 out (+bias)
// MODE 4: gated: v = Rf + (.+bias); Cf = ig*tanh(v) + fg*Gmem
// MODE 5: fp32 out (+bias) AND fp16 into mpi row m*9+8 (Ch = mpi base)
// ---------------------------------------------------------------------------
#define AST     144u
#define BST     272u
#define OFF_B   18432u
#define BUFSZ   35840u
#define NSTAGE  3
#define DSMEM   (NSTAGE * 35840)

template<int MODE>
__global__ __launch_bounds__(512)
void hgemm_kernel(const fp16* __restrict__ Ah, const fp16* __restrict__ Bh,
                  const float* __restrict__ bias,
                  const float* __restrict__ Rf,
                  const float* __restrict__ Gmem,
                  const float* __restrict__ Gates,
                  float* __restrict__ Cf, fp16* __restrict__ Ch,
                  int N, int K)
{
    extern __shared__ char sm_[];
    const uint32_t sbase = smem_u32(sm_);

    const int tid  = threadIdx.x;
    const int wid  = tid >> 5;
    const int lane = tid & 31;
    const int wm   = (wid & 3) << 5;
    const int wn   = (wid >> 2) << 5;
    const int bm   = blockIdx.y << 7;
    const int bn   = blockIdx.x << 7;

    const int arow = tid >> 2, aseg = tid & 3;
    const int brow = tid >> 4, bseg = tid & 15;

    const fp16* Ap = Ah + (size_t)(bm + arow) * K + (aseg << 3);
    const fp16* Bp = Bh + (size_t)brow * N + bn + (bseg << 3);
    const uint32_t aDst  = (uint32_t)arow * AST + (uint32_t)(aseg << 4);
    const uint32_t bDst  = (uint32_t)brow * BST + (uint32_t)(bseg << 4);
    const size_t  bRow2  = (size_t)32 * N;
    const uint32_t bDst2 = bDst + 32u * BST;

    const int nchunk = K >> 6;

    float acc[2][4][4];
    #pragma unroll
    for (int i = 0; i < 2; i++)
        #pragma unroll
        for (int j = 0; j < 4; j++)
            #pragma unroll
            for (int k = 0; k < 4; k++) acc[i][j][k] = 0.f;

    #pragma unroll
    for (int s = 0; s < NSTAGE - 1; s++) {
        const uint32_t sb = sbase + (uint32_t)s * BUFSZ;
        cp16(sb + aDst,        Ap + (s << 6));
        cp16(sb + aDst + 64u,  Ap + (s << 6) + 32);
        cp16(sb + OFF_B + bDst,  Bp + (size_t)(s << 6) * N);
        cp16(sb + OFF_B + bDst2, Bp + bRow2 + (size_t)(s << 6) * N);
        CP_COMMIT();
    }

    const uint32_t aOffBase = (uint32_t)(wm + (lane & 15)) * AST
                            + (uint32_t)((lane >> 4) << 4);
    const uint32_t bOffBase = (uint32_t)(lane & 15) * BST
                            + (uint32_t)(wn << 1) + (uint32_t)((lane >> 4) << 4);

    #pragma unroll 1
    for (int c = 0; c < nchunk; c++) {
        CP_WAIT();
        __syncthreads();

        const uint32_t tb = sbase + (uint32_t)(c % NSTAGE) * BUFSZ;

        #pragma unroll
        for (int ks = 0; ks < 4; ks++) {
            uint32_t ra[2][4], rb[2][4];
            const uint32_t aAd = tb + aOffBase + (uint32_t)(ks << 5);
            ldsm4(ra[0], aAd);
            ldsm4(ra[1], aAd + 16u * AST);
            const uint32_t bAd = tb + OFF_B + bOffBase + (uint32_t)(ks << 4) * BST;
            ldsm4t(rb[0], bAd);
            ldsm4t(rb[1], bAd + 32u);
            #pragma unroll
            for (int mt = 0; mt < 2; mt++)
                #pragma unroll
                for (int nt = 0; nt < 4; nt++)
                    mma16816(acc[mt][nt], ra[mt], &rb[nt >> 1][(nt & 1) << 1]);
        }

        const int cn = c + NSTAGE - 1;
        if (cn < nchunk) {
            const uint32_t nb = sbase + (uint32_t)(cn % NSTAGE) * BUFSZ;
            cp16(nb + aDst,        Ap + (cn << 6));
            cp16(nb + aDst + 64u,  Ap + (cn << 6) + 32);
            cp16(nb + OFF_B + bDst,  Bp + (size_t)(cn << 6) * N);
            cp16(nb + OFF_B + bDst2, Bp + bRow2 + (size_t)(cn << 6) * N);
        }
        CP_COMMIT();
    }

    // ---- epilogue ----
    #pragma unroll
    for (int mt = 0; mt < 2; mt++) {
        float ig0 = 0.f, fg0 = 0.f, ig1 = 0.f, fg1 = 0.f;
        if (MODE == 4) {
            const int mA = bm + wm + (mt << 4) + (lane >> 2);
            float2 gA = *(const float2*)(Gates + 2 * mA);
            float2 gB = *(const float2*)(Gates + 2 * (mA + 8));
            ig0 = gA.x; fg0 = gA.y;
            ig1 = gB.x; fg1 = gB.y;
        }
        #pragma unroll
        for (int nt = 0; nt < 4; nt++) {
            const int m = bm + wm + (mt << 4) + (lane >> 2);
            const int n = bn + wn + (nt << 3) + ((lane & 3) << 1);
            const float b0 = __ldg(&bias[n]);
            const float b1 = __ldg(&bias[n + 1]);
            float2 v0, v1;
            v0.x = acc[mt][nt][0] + b0;  v0.y = acc[mt][nt][1] + b1;
            v1.x = acc[mt][nt][2] + b0;  v1.y = acc[mt][nt][3] + b1;
            const size_t i0 = (size_t)m * N + n;
            const size_t i1 = (size_t)(m + 8) * N + n;
            if (MODE == 1) {
                v0.x = fmaxf(v0.x, 0.f); v0.y = fmaxf(v0.y, 0.f);
                v1.x = fmaxf(v1.x, 0.f); v1.y = fmaxf(v1.y, 0.f);
                *(fp162*)(Ch + i0) = __floats2half2_rn(v0.x, v0.y);
                *(fp162*)(Ch + i1) = __floats2half2_rn(v1.x, v1.y);
            }
            if (MODE == 3) {
                *(fp162*)(Ch + i0) = __floats2half2_rn(v0.x, v0.y);
                *(fp162*)(Ch + i1) = __floats2half2_rn(v1.x, v1.y);
            }
            if (MODE == 4) {
                float2 r0 = *(const float2*)(Rf + i0);
                float2 r1 = *(const float2*)(Rf + i1);
                float2 w0 = *(const float2*)(Gmem + i0);
                float2 w1 = *(const float2*)(Gmem + i1);
                float2 o0, o1;
                o0.x = fmaf(ig0, tanhf(v0.x + r0.x), fg0 * w0.x);
                o0.y = fmaf(ig0, tanhf(v0.y + r0.y), fg0 * w0.y);
                o1.x = fmaf(ig1, tanhf(v1.x + r1.x), fg1 * w1.x);
                o1.y = fmaf(ig1, tanhf(v1.y + r1.y), fg1 * w1.y);
                *(float2*)(Cf + i0) = o0;
                *(float2*)(Cf + i1) = o1;
            }
            if (MODE == 5) {
                *(float2*)(Cf + i0) = v0;
                *(float2*)(Cf + i1) = v1;
                // also write fp16 x into mpi row m*9+8
                const size_t p0 = ((size_t)m * SP1_ + S_) * M_ + n;
                const size_t p1 = ((size_t)(m + 8) * SP1_ + S_) * M_ + n;
                *(fp162*)(Ch + p0) = __floats2half2_rn(v0.x, v0.y);
                *(fp162*)(Ch + p1) = __floats2half2_rn(v1.x, v1.y);
            }
        }
    }
}

// ---------------------------------------------------------------------------
// gi[b,0:2] = x[b,:] @ kernel_gi + bias_gi   (one 128-thread block per b)
// ---------------------------------------------------------------------------
__global__ __launch_bounds__(128)
void gi_kernel(const float* __restrict__ x,
               const float* __restrict__ kgi,
               const float* __restrict__ bgi,
               float* __restrict__ gi)
{
    const int b   = blockIdx.x;
    const int tid = threadIdx.x;
    const float* xr = x + (size_t)b * M_;
    float g0 = 0.f, g1 = 0.f;
    for (int m = tid; m < M_; m += 128) {
        float xv = xr[m];
        g0 = fmaf(xv, kgi[2 * m + 0], g0);
        g1 = fmaf(xv, kgi[2 * m + 1], g1);
    }
    #pragma unroll
    for (int o = 16; o; o >>= 1) {
        g0 += __shfl_xor_sync(0xffffffffu, g0, o);
        g1 += __shfl_xor_sync(0xffffffffu, g1, o);
    }
    __shared__ float s0[4], s1[4];
    int w = tid >> 5, lane = tid & 31;
    if (lane == 0) { s0[w] = g0; s1[w] = g1; }
    __syncthreads();
    if (tid == 0) {
        gi[2 * b + 0] = s0[0] + s0[1] + s0[2] + s0[3] + bgi[0];
        gi[2 * b + 1] = s1[0] + s1[1] + s1[2] + s1[3] + bgi[1];
    }
}

// ---------------------------------------------------------------------------
// gates_kernel per (b,s)
// ---------------------------------------------------------------------------
__global__ __launch_bounds__(256)
void gates_kernel(const float* __restrict__ mem,
                  const float* __restrict__ kgm,
                  const float* __restrict__ bgm,
                  const float* __restrict__ gi,
                  float* __restrict__ gates)
{
    const int bs = blockIdx.x;
    const int b  = bs >> 3;
    const int tid = threadIdx.x;

    const float* mrow = mem + (size_t)bs * M_;

    float g0 = 0.f, g1 = 0.f;
    for (int m = tid; m < M_; m += 256) {
        float t = tanhf(mrow[m]);
        g0 = fmaf(t, kgm[2 * m + 0], g0);
        g1 = fmaf(t, kgm[2 * m + 1], g1);
    }
    #pragma unroll
    for (int o = 16; o; o >>= 1) {
        g0 += __shfl_xor_sync(0xffffffffu, g0, o);
        g1 += __shfl_xor_sync(0xffffffffu, g1, o);
    }
    __shared__ float s0[8], s1[8];
    int w = tid >> 5, lane = tid & 31;
    if (lane == 0) { s0[w] = g0; s1[w] = g1; }
    __syncthreads();
    if (tid == 0) {
        float G0 = 0.f, G1 = 0.f;
        #pragma unroll
        for (int i = 0; i < 8; i++) { G0 += s0[i]; G1 += s1[i]; }
        G0 += bgm[0] + gi[2 * b + 0];
        G1 += bgm[1] + gi[2 * b + 1] + 1.0f;
        gates[2 * bs + 0] = 1.f / (1.f + expf(-G0));
        gates[2 * bs + 1] = 1.f / (1.f + expf(-G1));
    }
}

// ---------------------------------------------------------------------------
// Attention per (b,h): m1 = res + softmax(q k^T) v   (compacted rows s<8)
// ---------------------------------------------------------------------------
__global__ __launch_bounds__(256)
void attn_kernel(const fp16* __restrict__ qkv,
                 const float* __restrict__ mem,
                 const float* __restrict__ x,
                 fp16* __restrict__ m1h, float* __restrict__ m1f)
{
    const int bh = blockIdx.x;
    const int b  = bh >> 3;
    const int h  = bh & 7;

    __shared__ float q [SP1_][128];
    __shared__ float kk[SP1_][128];
    __shared__ float vv[SP1_][128];
    __shared__ float sc[SP1_][SP1_];

    const float scale = rsqrtf((float)QKV_);
    const int tid = threadIdx.x;

    for (int i = tid; i < SP1_ * 64; i += 256) {
        int s = i >> 6, d = (i & 63) << 1;
        const fp16* base = qkv + ((size_t)(b * SP1_ + s)) * TOT_ + h * QKV_;
        fp162 qv  = *(const fp162*)(base + d);
        fp162 kv  = *(const fp162*)(base + 128 + d);
        fp162 vv2 = *(const fp162*)(base + 256 + d);
        q [s][d]     = __half2float(qv.x) * scale;
        q [s][d + 1] = __half2float(qv.y) * scale;
        kk[s][d]     = __half2float(kv.x);
        kk[s][d + 1] = __half2float(kv.y);
        vv[s][d]     = __half2float(vv2.x);
        vv[s][d + 1] = __half2float(vv2.y);
    }
    __syncthreads();

    const int w = tid >> 5, lane = tid & 31;
    for (int idx = w; idx < SP1_ * SP1_; idx += 8) {
        int i = idx / SP1_, j = idx - i * SP1_;
        float s = 0.f;
        for (int d = lane; d < 128; d += 32) s = fmaf(q[i][d], kk[j][d], s);
        #pragma unroll
        for (int o = 16; o; o >>= 1) s += __shfl_xor_sync(0xffffffffu, s, o);
        if (lane == 0) sc[i][j] = s;
    }
    __syncthreads();

    if (tid < SP1_) {
        float mx = -1e30f;
        #pragma unroll
        for (int j = 0; j < SP1_; j++) mx = fmaxf(mx, sc[tid][j]);
        float e[SP1_], sum = 0.f;
        #pragma unroll
        for (int j = 0; j < SP1_; j++) { e[j] = expf(sc[tid][j] - mx); sum += e[j]; }
        float inv = 1.f / sum;
        #pragma unroll
        for (int j = 0; j < SP1_; j++) sc[tid][j] = e[j] * inv;
    }
    __syncthreads();

    for (int i = tid; i < S_ * 64; i += 256) {
        int s  = i >> 6;
        int d  = (i & 63) << 1;
        float a0 = 0.f, a1 = 0.f;
        #pragma unroll
        for (int j = 0; j < SP1_; j++) {
            a0 = fmaf(sc[s][j], vv[j][d],     a0);
            a1 = fmaf(sc[s][j], vv[j][d + 1], a1);
        }
        const float* src = mem + (((size_t)b * S_ + s) << 10);
        float2 r = *(const float2*)(src + h * 128 + d);
        float v0 = r.x + a0;
        float v1 = r.y + a1;
        size_t o = ((size_t)(b * S_ + s)) * M_ + h * 128 + d;
        *(fp162*)(m1h + o) = __floats2half2_rn(v0, v1);
        *(float2*)(m1f + o) = make_float2(v0, v1);
    }
}

// ---------------------------------------------------------------------------
// kernel_launch
// ---------------------------------------------------------------------------
extern "C" void kernel_launch(void* const* d_in, const int* in_sizes, int n_in,
                              void* d_out, int out_size)
{
    const float* inputs   = (const float*)d_in[0];
    const float* memory   = (const float*)d_in[1];
    const float* k_qkv    = (const float*)d_in[2];
    const float* b_qkv    = (const float*)d_in[3];
    const float* k_gi     = (const float*)d_in[4];
    const float* b_gi     = (const float*)d_in[5];
    const float* k_gm     = (const float*)d_in[6];
    const float* b_gm     = (const float*)d_in[7];
    const float* k_in     = (const float*)d_in[8];
    const float* b_in     = (const float*)d_in[9];
    const float* mlp_k0   = (const float*)d_in[10];
    const float* mlp_b0   = (const float*)d_in[11];
    const float* mlp_k1   = (const float*)d_in[12];
    const float* mlp_b1   = (const float*)d_in[13];
    float* out = (float*)d_out;

    float *px, *pm1f, *pgi, *pgates;
    fp16 *pqkvh, *pinh, *pw, *pmpih, *pm1h, *phh;
    cudaGetSymbolAddress((void**)&px,     g_x);
    cudaGetSymbolAddress((void**)&pm1f,   g_m1f);
    cudaGetSymbolAddress((void**)&pgi,    g_gi);
    cudaGetSymbolAddress((void**)&pgates, g_gates);
    cudaGetSymbolAddress((void**)&pqkvh,  g_qkv_h);
    cudaGetSymbolAddress((void**)&pinh,   g_in_h);
    cudaGetSymbolAddress((void**)&pw,     g_w);
    cudaGetSymbolAddress((void**)&pmpih,  g_mpi_h);
    cudaGetSymbolAddress((void**)&pm1h,   g_m1_h);
    cudaGetSymbolAddress((void**)&phh,    g_h_h);

    const size_t MM = (size_t)M_ * M_;
    fp16 *kinW = pw;
    fp16 *kqkW = pw + MM;
    fp16 *k0W  = pw + 4 * MM;
    fp16 *k1W  = pw + 5 * MM;

    cudaFuncSetAttribute(hgemm_kernel<1>, cudaFuncAttributeMaxDynamicSharedMemorySize, DSMEM);
    cudaFuncSetAttribute(hgemm_kernel<3>, cudaFuncAttributeMaxDynamicSharedMemorySize, DSMEM);
    cudaFuncSetAttribute(hgemm_kernel<4>, cudaFuncAttributeMaxDynamicSharedMemorySize, DSMEM);
    cudaFuncSetAttribute(hgemm_kernel<5>, cudaFuncAttributeMaxDynamicSharedMemorySize, DSMEM);

    // 0. fused conversion: inputs + 4 weights + memory->mpi (one launch)
    {
        const int n_in4 = B_ * M_ / 4;
        const int n_1M4 = (int)(MM / 4);
        const int n_3M4 = (int)(3 * MM / 4);
        const int n_mem4 = CROWS_ * M_ / 4;
        const int e0 = n_in4;
        const int e1 = e0 + n_1M4;
        const int e2 = e1 + n_3M4;
        const int e3 = e2 + n_1M4;
        const int e4 = e3 + n_1M4;
        const int e5 = e4 + n_mem4;
        cvt6_kernel<<<(e5 + 255) / 256, 256>>>(
            inputs, pinh, e0,
            k_in,   kinW, e1,
            k_qkv,  kqkW, e2,
            mlp_k0, k0W,  e3,
            mlp_k1, k1W,  e4,
            memory, pmpih, e5);
    }

    // 1. x = inputs @ kernel_in + bias_in  (fp32 out + fp16 into mpi row s==8)
    hgemm_kernel<5><<<dim3(M_ / 128, B_ / 128), 512, DSMEM>>>(
        pinh, kinW, b_in, nullptr, nullptr, nullptr, px, pmpih, M_, M_);

    // 2. gi + gates
    gi_kernel<<<B_, 128>>>(px, k_gi, b_gi, pgi);
    gates_kernel<<<CROWS_, 256>>>(memory, k_gm, b_gm, pgi, pgates);

    // 3. qkv = mpi @ kernel_qkv + bias_qkv   (fp16 out)
    hgemm_kernel<3><<<dim3(TOT_ / 128, ROWS_ / 128), 512, DSMEM>>>(
        pmpih, kqkW, b_qkv, nullptr, nullptr, nullptr, nullptr, pqkvh, TOT_, M_);

    // 4. attention + fp32 residual -> compacted m1 (fp16 + fp32)
    attn_kernel<<<B_ * H_, 256>>>(pqkvh, memory, px, pm1h, pm1f);

    // 5. h = relu(m1 @ mlp_k0 + mlp_b0) -> fp16
    hgemm_kernel<1><<<dim3(M_ / 128, CROWS_ / 128), 512, DSMEM>>>(
        pm1h, k0W, mlp_b0, nullptr, nullptr, nullptr, nullptr, phh, M_, M_);

    // 6. out = ig*tanh(m1 + h @ mlp_k1 + mlp_b1) + fg*mem   (fused gate)
    hgemm_kernel<4><<<dim3(M_ / 128, CROWS_ / 128), 512, DSMEM>>>(
        phh, k1W, mlp_b1, pm1f, memory, pgates, out, nullptr, M_, M_);
}

// round 15
// speedup vs baseline: 1.1841x; 1.0050x over previous
#include <cuda_runtime.h>
#include <cuda_fp16.h>
#include <math.h>
#include <stdint.h>

// ---------------------------------------------------------------------------
// RelationalMemoryCell  (B=2048, S=8, H=8, M=1024, QKV=384, TOT=3072)
// Round 15: R14 + fast MUFU tanh (gates_kernel + MODE-4 epilogue).
//   tanh(x) = 1 - 2/(e^{2x}+1) via __expf/__fdividef  (~1e-6 error).
// ---------------------------------------------------------------------------

#define B_     2048
#define S_     8
#define H_     8
#define M_     1024
#define QKV_   384
#define TOT_   3072
#define SP1_   9
#define ROWS_  (B_*SP1_)   // 18432
#define CROWS_ (B_*S_)     // 16384

typedef __half  fp16;
typedef __half2 fp162;

// ---- global scratch (allocation-free rule) ----
__device__ __align__(256) float g_x    [(size_t)B_    * M_];
__device__ __align__(256) float g_m1f  [(size_t)CROWS_* M_];
__device__ __align__(256) float g_gi   [(size_t)B_ * 2];
__device__ __align__(256) float g_gates[(size_t)CROWS_ * 2];

__device__ __align__(256) fp16 g_qkv_h [(size_t)ROWS_ * TOT_];
__device__ __align__(256) fp16 g_in_h  [(size_t)B_ * M_];
__device__ __align__(256) fp16 g_w     [(size_t)6 * M_ * M_];
__device__ __align__(256) fp16 g_mpi_h [(size_t)ROWS_ * M_];
__device__ __align__(256) fp16 g_m1_h  [(size_t)CROWS_ * M_];
__device__ __align__(256) fp16 g_h_h   [(size_t)CROWS_ * M_];

// ---------------------------------------------------------------------------
// helpers
// ---------------------------------------------------------------------------
__device__ __forceinline__ uint32_t smem_u32(const void* p) {
    uint32_t a;
    asm("{ .reg .u64 t; cvta.to.shared.u64 t, %1; cvt.u32.u64 %0, t; }"
        : "=r"(a) : "l"(p));
    return a;
}
__device__ __forceinline__ void cp16(uint32_t dst, const void* src) {
    asm volatile("cp.async.cg.shared.global [%0], [%1], 16;"
                 :: "r"(dst), "l"(src) : "memory");
}
#define CP_COMMIT() asm volatile("cp.async.commit_group;" ::: "memory")
#define CP_WAIT()   asm volatile("cp.async.wait_group 1;"  ::: "memory")

__device__ __forceinline__ void ldsm4(uint32_t* r, uint32_t a) {
    asm volatile("ldmatrix.sync.aligned.m8n8.x4.shared.b16 {%0,%1,%2,%3}, [%4];"
        : "=r"(r[0]), "=r"(r[1]), "=r"(r[2]), "=r"(r[3]) : "r"(a));
}
__device__ __forceinline__ void ldsm4t(uint32_t* r, uint32_t a) {
    asm volatile("ldmatrix.sync.aligned.m8n8.x4.trans.shared.b16 {%0,%1,%2,%3}, [%4];"
        : "=r"(r[0]), "=r"(r[1]), "=r"(r[2]), "=r"(r[3]) : "r"(a));
}
__device__ __forceinline__ void mma16816(float* c, const uint32_t* a, const uint32_t* b) {
    asm volatile(
        "mma.sync.aligned.m16n8k16.row.col.f32.f16.f16.f32 "
        "{%0,%1,%2,%3}, {%4,%5,%6,%7}, {%8,%9}, {%0,%1,%2,%3};"
        : "+f"(c[0]), "+f"(c[1]), "+f"(c[2]), "+f"(c[3])
        : "r"(a[0]), "r"(a[1]), "r"(a[2]), "r"(a[3]), "r"(b[0]), "r"(b[1]));
}

// fast tanh via MUFU: tanh(x) = 1 - 2/(e^{2x}+1)
// e -> inf gives 1, e -> 0 gives -1; ~1e-6 abs error.
__device__ __forceinline__ float ftanh(float x) {
    float e = __expf(2.f * x);
    return 1.f - __fdividef(2.f, e + 1.f);
}

// ---------------------------------------------------------------------------
// cvt6_kernel: fused fp32 -> fp16. Regions 0..4 contiguous (inputs + 4
// weights). Region 5 = memory -> mpi rows (strided: row b*8+s -> b*9+s).
// ---------------------------------------------------------------------------
__global__ void cvt6_kernel(const float* __restrict__ s0, fp16* __restrict__ d0, int e0,
                            const float* __restrict__ s1, fp16* __restrict__ d1, int e1,
                            const float* __restrict__ s2, fp16* __restrict__ d2, int e2,
                            const float* __restrict__ s3, fp16* __restrict__ d3, int e3,
                            const float* __restrict__ s4, fp16* __restrict__ d4, int e4,
                            const float* __restrict__ mem, fp16* __restrict__ mpi, int e5)
{
    int i = blockIdx.x * blockDim.x + threadIdx.x;
    if (i >= e5) return;
    if (i >= e4) {
        int j = i - e4;
        float4 v = __ldg((const float4*)mem + j);
        int row    = j >> 8;
        int within = (j & 255) << 1;
        int b = row >> 3, s = row & 7;
        fp162* D = (fp162*)mpi + (((size_t)(b * SP1_ + s)) << 9) + within;
        D[0] = __floats2half2_rn(v.x, v.y);
        D[1] = __floats2half2_rn(v.z, v.w);
        return;
    }
    const float* s; fp16* d; int base;
    if      (i < e0) { s = s0; d = d0; base = 0;  }
    else if (i < e1) { s = s1; d = d1; base = e0; }
    else if (i < e2) { s = s2; d = d2; base = e1; }
    else if (i < e3) { s = s3; d = d3; base = e2; }
    else             { s = s4; d = d4; base = e3; }
    int j = i - base;
    float4 v = __ldg((const float4*)s + j);
    fp162* D = (fp162*)d + 2 * j;
    D[0] = __floats2half2_rn(v.x, v.y);
    D[1] = __floats2half2_rn(v.z, v.w);
}

// ---------------------------------------------------------------------------
// fp16 HMMA GEMM, 512 threads (16 warps, 4x4, 32x32 warp tile),
// 128x128 CTA tile, BK=64, 3-stage cp.async.
// MODE 1: relu(+bias) -> fp16 out (Ch)
// MODE 3: fp16 out (+bias)
// MODE 4: gated: v = Rf + (.+bias); Cf = ig*tanh(v) + fg*Gmem
// MODE 5: fp32 out (+bias) AND fp16 into mpi row m*9+8
// ---------------------------------------------------------------------------
#define AST     144u
#define BST     272u
#define OFF_B   18432u
#define BUFSZ   35840u
#define NSTAGE  3
#define DSMEM   (NSTAGE * 35840)

template<int MODE>
__global__ __launch_bounds__(512)
void hgemm_kernel(const fp16* __restrict__ Ah, const fp16* __restrict__ Bh,
                  const float* __restrict__ bias,
                  const float* __restrict__ Rf,
                  const float* __restrict__ Gmem,
                  const float* __restrict__ Gates,
                  float* __restrict__ Cf, fp16* __restrict__ Ch,
                  int N, int K)
{
    extern __shared__ char sm_[];
    const uint32_t sbase = smem_u32(sm_);

    const int tid  = threadIdx.x;
    const int wid  = tid >> 5;
    const int lane = tid & 31;
    const int wm   = (wid & 3) << 5;
    const int wn   = (wid >> 2) << 5;
    const int bm   = blockIdx.y << 7;
    const int bn   = blockIdx.x << 7;

    const int arow = tid >> 2, aseg = tid & 3;
    const int brow = tid >> 4, bseg = tid & 15;

    const fp16* Ap = Ah + (size_t)(bm + arow) * K + (aseg << 3);
    const fp16* Bp = Bh + (size_t)brow * N + bn + (bseg << 3);
    const uint32_t aDst  = (uint32_t)arow * AST + (uint32_t)(aseg << 4);
    const uint32_t bDst  = (uint32_t)brow * BST + (uint32_t)(bseg << 4);
    const size_t  bRow2  = (size_t)32 * N;
    const uint32_t bDst2 = bDst + 32u * BST;

    const int nchunk = K >> 6;

    float acc[2][4][4];
    #pragma unroll
    for (int i = 0; i < 2; i++)
        #pragma unroll
        for (int j = 0; j < 4; j++)
            #pragma unroll
            for (int k = 0; k < 4; k++) acc[i][j][k] = 0.f;

    #pragma unroll
    for (int s = 0; s < NSTAGE - 1; s++) {
        const uint32_t sb = sbase + (uint32_t)s * BUFSZ;
        cp16(sb + aDst,        Ap + (s << 6));
        cp16(sb + aDst + 64u,  Ap + (s << 6) + 32);
        cp16(sb + OFF_B + bDst,  Bp + (size_t)(s << 6) * N);
        cp16(sb + OFF_B + bDst2, Bp + bRow2 + (size_t)(s << 6) * N);
        CP_COMMIT();
    }

    const uint32_t aOffBase = (uint32_t)(wm + (lane & 15)) * AST
                            + (uint32_t)((lane >> 4) << 4);
    const uint32_t bOffBase = (uint32_t)(lane & 15) * BST
                            + (uint32_t)(wn << 1) + (uint32_t)((lane >> 4) << 4);

    #pragma unroll 1
    for (int c = 0; c < nchunk; c++) {
        CP_WAIT();
        __syncthreads();

        const uint32_t tb = sbase + (uint32_t)(c % NSTAGE) * BUFSZ;

        #pragma unroll
        for (int ks = 0; ks < 4; ks++) {
            uint32_t ra[2][4], rb[2][4];
            const uint32_t aAd = tb + aOffBase + (uint32_t)(ks << 5);
            ldsm4(ra[0], aAd);
            ldsm4(ra[1], aAd + 16u * AST);
            const uint32_t bAd = tb + OFF_B + bOffBase + (uint32_t)(ks << 4) * BST;
            ldsm4t(rb[0], bAd);
            ldsm4t(rb[1], bAd + 32u);
            #pragma unroll
            for (int mt = 0; mt < 2; mt++)
                #pragma unroll
                for (int nt = 0; nt < 4; nt++)
                    mma16816(acc[mt][nt], ra[mt], &rb[nt >> 1][(nt & 1) << 1]);
        }

        const int cn = c + NSTAGE - 1;
        if (cn < nchunk) {
            const uint32_t nb = sbase + (uint32_t)(cn % NSTAGE) * BUFSZ;
            cp16(nb + aDst,        Ap + (cn << 6));
            cp16(nb + aDst + 64u,  Ap + (cn << 6) + 32);
            cp16(nb + OFF_B + bDst,  Bp + (size_t)(cn << 6) * N);
            cp16(nb + OFF_B + bDst2, Bp + bRow2 + (size_t)(cn << 6) * N);
        }
        CP_COMMIT();
    }

    // ---- epilogue ----
    #pragma unroll
    for (int mt = 0; mt < 2; mt++) {
        float ig0 = 0.f, fg0 = 0.f, ig1 = 0.f, fg1 = 0.f;
        if (MODE == 4) {
            const int mA = bm + wm + (mt << 4) + (lane >> 2);
            float2 gA = *(const float2*)(Gates + 2 * mA);
            float2 gB = *(const float2*)(Gates + 2 * (mA + 8));
            ig0 = gA.x; fg0 = gA.y;
            ig1 = gB.x; fg1 = gB.y;
        }
        #pragma unroll
        for (int nt = 0; nt < 4; nt++) {
            const int m = bm + wm + (mt << 4) + (lane >> 2);
            const int n = bn + wn + (nt << 3) + ((lane & 3) << 1);
            const float b0 = __ldg(&bias[n]);
            const float b1 = __ldg(&bias[n + 1]);
            float2 v0, v1;
            v0.x = acc[mt][nt][0] + b0;  v0.y = acc[mt][nt][1] + b1;
            v1.x = acc[mt][nt][2] + b0;  v1.y = acc[mt][nt][3] + b1;
            const size_t i0 = (size_t)m * N + n;
            const size_t i1 = (size_t)(m + 8) * N + n;
            if (MODE == 1) {
                v0.x = fmaxf(v0.x, 0.f); v0.y = fmaxf(v0.y, 0.f);
                v1.x = fmaxf(v1.x, 0.f); v1.y = fmaxf(v1.y, 0.f);
                *(fp162*)(Ch + i0) = __floats2half2_rn(v0.x, v0.y);
                *(fp162*)(Ch + i1) = __floats2half2_rn(v1.x, v1.y);
            }
            if (MODE == 3) {
                *(fp162*)(Ch + i0) = __floats2half2_rn(v0.x, v0.y);
                *(fp162*)(Ch + i1) = __floats2half2_rn(v1.x, v1.y);
            }
            if (MODE == 4) {
                float2 r0 = *(const float2*)(Rf + i0);
                float2 r1 = *(const float2*)(Rf + i1);
                float2 w0 = *(const float2*)(Gmem + i0);
                float2 w1 = *(const float2*)(Gmem + i1);
                float2 o0, o1;
                o0.x = fmaf(ig0, ftanh(v0.x + r0.x), fg0 * w0.x);
                o0.y = fmaf(ig0, ftanh(v0.y + r0.y), fg0 * w0.y);
                o1.x = fmaf(ig1, ftanh(v1.x + r1.x), fg1 * w1.x);
                o1.y = fmaf(ig1, ftanh(v1.y + r1.y), fg1 * w1.y);
                *(float2*)(Cf + i0) = o0;
                *(float2*)(Cf + i1) = o1;
            }
            if (MODE == 5) {
                *(float2*)(Cf + i0) = v0;
                *(float2*)(Cf + i1) = v1;
                const size_t p0 = ((size_t)m * SP1_ + S_) * M_ + n;
                const size_t p1 = ((size_t)(m + 8) * SP1_ + S_) * M_ + n;
                *(fp162*)(Ch + p0) = __floats2half2_rn(v0.x, v0.y);
                *(fp162*)(Ch + p1) = __floats2half2_rn(v1.x, v1.y);
            }
        }
    }
}

// ---------------------------------------------------------------------------
// gi[b,0:2] = x[b,:] @ kernel_gi + bias_gi   (one 128-thread block per b)
// ---------------------------------------------------------------------------
__global__ __launch_bounds__(128)
void gi_kernel(const float* __restrict__ x,
               const float* __restrict__ kgi,
               const float* __restrict__ bgi,
               float* __restrict__ gi)
{
    const int b   = blockIdx.x;
    const int tid = threadIdx.x;
    const float* xr = x + (size_t)b * M_;
    float g0 = 0.f, g1 = 0.f;
    for (int m = tid; m < M_; m += 128) {
        float xv = xr[m];
        g0 = fmaf(xv, kgi[2 * m + 0], g0);
        g1 = fmaf(xv, kgi[2 * m + 1], g1);
    }
    #pragma unroll
    for (int o = 16; o; o >>= 1) {
        g0 += __shfl_xor_sync(0xffffffffu, g0, o);
        g1 += __shfl_xor_sync(0xffffffffu, g1, o);
    }
    __shared__ float s0[4], s1[4];
    int w = tid >> 5, lane = tid & 31;
    if (lane == 0) { s0[w] = g0; s1[w] = g1; }
    __syncthreads();
    if (tid == 0) {
        gi[2 * b + 0] = s0[0] + s0[1] + s0[2] + s0[3] + bgi[0];
        gi[2 * b + 1] = s1[0] + s1[1] + s1[2] + s1[3] + bgi[1];
    }
}

// ---------------------------------------------------------------------------
// gates_kernel per (b,s): fast tanh
// ---------------------------------------------------------------------------
__global__ __launch_bounds__(256)
void gates_kernel(const float* __restrict__ mem,
                  const float* __restrict__ kgm,
                  const float* __restrict__ bgm,
                  const float* __restrict__ gi,
                  float* __restrict__ gates)
{
    const int bs = blockIdx.x;
    const int b  = bs >> 3;
    const int tid = threadIdx.x;

    const float* mrow = mem + (size_t)bs * M_;

    float g0 = 0.f, g1 = 0.f;
    for (int m = tid; m < M_; m += 256) {
        float t = ftanh(mrow[m]);
        g0 = fmaf(t, kgm[2 * m + 0], g0);
        g1 = fmaf(t, kgm[2 * m + 1], g1);
    }
    #pragma unroll
    for (int o = 16; o; o >>= 1) {
        g0 += __shfl_xor_sync(0xffffffffu, g0, o);
        g1 += __shfl_xor_sync(0xffffffffu, g1, o);
    }
    __shared__ float s0[8], s1[8];
    int w = tid >> 5, lane = tid & 31;
    if (lane == 0) { s0[w] = g0; s1[w] = g1; }
    __syncthreads();
    if (tid == 0) {
        float G0 = 0.f, G1 = 0.f;
        #pragma unroll
        for (int i = 0; i < 8; i++) { G0 += s0[i]; G1 += s1[i]; }
        G0 += bgm[0] + gi[2 * b + 0];
        G1 += bgm[1] + gi[2 * b + 1] + 1.0f;
        gates[2 * bs + 0] = 1.f / (1.f + __expf(-G0));
        gates[2 * bs + 1] = 1.f / (1.f + __expf(-G1));
    }
}

// ---------------------------------------------------------------------------
// Attention per (b,h): m1 = res + softmax(q k^T) v   (compacted rows s<8)
// ---------------------------------------------------------------------------
__global__ __launch_bounds__(256)
void attn_kernel(const fp16* __restrict__ qkv,
                 const float* __restrict__ mem,
                 const float* __restrict__ x,
                 fp16* __restrict__ m1h, float* __restrict__ m1f)
{
    const int bh = blockIdx.x;
    const int b  = bh >> 3;
    const int h  = bh & 7;

    __shared__ float q [SP1_][128];
    __shared__ float kk[SP1_][128];
    __shared__ float vv[SP1_][128];
    __shared__ float sc[SP1_][SP1_];

    const float scale = rsqrtf((float)QKV_);
    const int tid = threadIdx.x;

    for (int i = tid; i < SP1_ * 64; i += 256) {
        int s = i >> 6, d = (i & 63) << 1;
        const fp16* base = qkv + ((size_t)(b * SP1_ + s)) * TOT_ + h * QKV_;
        fp162 qv  = *(const fp162*)(base + d);
        fp162 kv  = *(const fp162*)(base + 128 + d);
        fp162 vv2 = *(const fp162*)(base + 256 + d);
        q [s][d]     = __half2float(qv.x) * scale;
        q [s][d + 1] = __half2float(qv.y) * scale;
        kk[s][d]     = __half2float(kv.x);
        kk[s][d + 1] = __half2float(kv.y);
        vv[s][d]     = __half2float(vv2.x);
        vv[s][d + 1] = __half2float(vv2.y);
    }
    __syncthreads();

    const int w = tid >> 5, lane = tid & 31;
    for (int idx = w; idx < SP1_ * SP1_; idx += 8) {
        int i = idx / SP1_, j = idx - i * SP1_;
        float s = 0.f;
        for (int d = lane; d < 128; d += 32) s = fmaf(q[i][d], kk[j][d], s);
        #pragma unroll
        for (int o = 16; o; o >>= 1) s += __shfl_xor_sync(0xffffffffu, s, o);
        if (lane == 0) sc[i][j] = s;
    }
    __syncthreads();

    if (tid < SP1_) {
        float mx = -1e30f;
        #pragma unroll
        for (int j = 0; j < SP1_; j++) mx = fmaxf(mx, sc[tid][j]);
        float e[SP1_], sum = 0.f;
        #pragma unroll
        for (int j = 0; j < SP1_; j++) { e[j] = expf(sc[tid][j] - mx); sum += e[j]; }
        float inv = 1.f / sum;
        #pragma unroll
        for (int j = 0; j < SP1_; j++) sc[tid][j] = e[j] * inv;
    }
    __syncthreads();

    for (int i = tid; i < S_ * 64; i += 256) {
        int s  = i >> 6;
        int d  = (i & 63) << 1;
        float a0 = 0.f, a1 = 0.f;
        #pragma unroll
        for (int j = 0; j < SP1_; j++) {
            a0 = fmaf(sc[s][j], vv[j][d],     a0);
            a1 = fmaf(sc[s][j], vv[j][d + 1], a1);
        }
        const float* src = mem + (((size_t)b * S_ + s) << 10);
        float2 r = *(const float2*)(src + h * 128 + d);
        float v0 = r.x + a0;
        float v1 = r.y + a1;
        size_t o = ((size_t)(b * S_ + s)) * M_ + h * 128 + d;
        *(fp162*)(m1h + o) = __floats2half2_rn(v0, v1);
        *(float2*)(m1f + o) = make_float2(v0, v1);
    }
}

// ---------------------------------------------------------------------------
// kernel_launch
// ---------------------------------------------------------------------------
extern "C" void kernel_launch(void* const* d_in, const int* in_sizes, int n_in,
                              void* d_out, int out_size)
{
    const float* inputs   = (const float*)d_in[0];
    const float* memory   = (const float*)d_in[1];
    const float* k_qkv    = (const float*)d_in[2];
    const float* b_qkv    = (const float*)d_in[3];
    const float* k_gi     = (const float*)d_in[4];
    const float* b_gi     = (const float*)d_in[5];
    const float* k_gm     = (const float*)d_in[6];
    const float* b_gm     = (const float*)d_in[7];
    const float* k_in     = (const float*)d_in[8];
    const float* b_in     = (const float*)d_in[9];
    const float* mlp_k0   = (const float*)d_in[10];
    const float* mlp_b0   = (const float*)d_in[11];
    const float* mlp_k1   = (const float*)d_in[12];
    const float* mlp_b1   = (const float*)d_in[13];
    float* out = (float*)d_out;

    float *px, *pm1f, *pgi, *pgates;
    fp16 *pqkvh, *pinh, *pw, *pmpih, *pm1h, *phh;
    cudaGetSymbolAddress((void**)&px,     g_x);
    cudaGetSymbolAddress((void**)&pm1f,   g_m1f);
    cudaGetSymbolAddress((void**)&pgi,    g_gi);
    cudaGetSymbolAddress((void**)&pgates, g_gates);
    cudaGetSymbolAddress((void**)&pqkvh,  g_qkv_h);
    cudaGetSymbolAddress((void**)&pinh,   g_in_h);
    cudaGetSymbolAddress((void**)&pw,     g_w);
    cudaGetSymbolAddress((void**)&pmpih,  g_mpi_h);
    cudaGetSymbolAddress((void**)&pm1h,   g_m1_h);
    cudaGetSymbolAddress((void**)&phh,    g_h_h);

    const size_t MM = (size_t)M_ * M_;
    fp16 *kinW = pw;
    fp16 *kqkW = pw + MM;
    fp16 *k0W  = pw + 4 * MM;
    fp16 *k1W  = pw + 5 * MM;

    cudaFuncSetAttribute(hgemm_kernel<1>, cudaFuncAttributeMaxDynamicSharedMemorySize, DSMEM);
    cudaFuncSetAttribute(hgemm_kernel<3>, cudaFuncAttributeMaxDynamicSharedMemorySize, DSMEM);
    cudaFuncSetAttribute(hgemm_kernel<4>, cudaFuncAttributeMaxDynamicSharedMemorySize, DSMEM);
    cudaFuncSetAttribute(hgemm_kernel<5>, cudaFuncAttributeMaxDynamicSharedMemorySize, DSMEM);

    // 0. fused conversion: inputs + 4 weights + memory->mpi (one launch)
    {
        const int n_in4 = B_ * M_ / 4;
        const int n_1M4 = (int)(MM / 4);
        const int n_3M4 = (int)(3 * MM / 4);
        const int n_mem4 = CROWS_ * M_ / 4;
        const int e0 = n_in4;
        const int e1 = e0 + n_1M4;
        const int e2 = e1 + n_3M4;
        const int e3 = e2 + n_1M4;
        const int e4 = e3 + n_1M4;
        const int e5 = e4 + n_mem4;
        cvt6_kernel<<<(e5 + 255) / 256, 256>>>(
            inputs, pinh, e0,
            k_in,   kinW, e1,
            k_qkv,  kqkW, e2,
            mlp_k0, k0W,  e3,
            mlp_k1, k1W,  e4,
            memory, pmpih, e5);
    }

    // 1. x = inputs @ kernel_in + bias_in  (fp32 out + fp16 into mpi row s==8)
    hgemm_kernel<5><<<dim3(M_ / 128, B_ / 128), 512, DSMEM>>>(
        pinh, kinW, b_in, nullptr, nullptr, nullptr, px, pmpih, M_, M_);

    // 2. gi + gates
    gi_kernel<<<B_, 128>>>(px, k_gi, b_gi, pgi);
    gates_kernel<<<CROWS_, 256>>>(memory, k_gm, b_gm, pgi, pgates);

    // 3. qkv = mpi @ kernel_qkv + bias_qkv   (fp16 out)
    hgemm_kernel<3><<<dim3(TOT_ / 128, ROWS_ / 128), 512, DSMEM>>>(
        pmpih, kqkW, b_qkv, nullptr, nullptr, nullptr, nullptr, pqkvh, TOT_, M_);

    // 4. attention + fp32 residual -> compacted m1 (fp16 + fp32)
    attn_kernel<<<B_ * H_, 256>>>(pqkvh, memory, px, pm1h, pm1f);

    // 5. h = relu(m1 @ mlp_k0 + mlp_b0) -> fp16
    hgemm_kernel<1><<<dim3(M_ / 128, CROWS_ / 128), 512, DSMEM>>>(
        pm1h, k0W, mlp_b0, nullptr, nullptr, nullptr, nullptr, phh, M_, M_);

    // 6. out = ig*tanh(m1 + h @ mlp_k1 + mlp_b1) + fg*mem   (fused gate)
    hgemm_kernel<4><<<dim3(M_ / 128, CROWS_ / 128), 512, DSMEM>>>(
        phh, k1W, mlp_b1, pm1f, memory, pgates, out, nullptr, M_, M_);
}

// round 16
// speedup vs baseline: 1.2325x; 1.0409x over previous
#include <cuda_runtime.h>
#include <cuda_fp16.h>
#include <math.h>
#include <stdint.h>

// ---------------------------------------------------------------------------
// RelationalMemoryCell  (B=2048, S=8, H=8, M=1024, QKV=384, TOT=3072)
// Round 16: R15 + gates dot-product fused into cvt6's memory pass
// (warp-reduced partials, no atomics) + tiny finalize kernel.
// gates_kernel (41 us redundant memory re-read) deleted.
// ---------------------------------------------------------------------------

#define B_     2048
#define S_     8
#define H_     8
#define M_     1024
#define QKV_   384
#define TOT_   3072
#define SP1_   9
#define ROWS_  (B_*SP1_)   // 18432
#define CROWS_ (B_*S_)     // 16384

typedef __half  fp16;
typedef __half2 fp162;

// ---- global scratch (allocation-free rule) ----
__device__ __align__(256) float g_x    [(size_t)B_    * M_];
__device__ __align__(256) float g_m1f  [(size_t)CROWS_* M_];
__device__ __align__(256) float g_gi   [(size_t)B_ * 2];
__device__ __align__(256) float g_gates[(size_t)CROWS_ * 2];
__device__ __align__(256) float g_gpart[(size_t)CROWS_ * 16];   // 8 warps x 2 gates

__device__ __align__(256) fp16 g_qkv_h [(size_t)ROWS_ * TOT_];
__device__ __align__(256) fp16 g_in_h  [(size_t)B_ * M_];
__device__ __align__(256) fp16 g_w     [(size_t)6 * M_ * M_];
__device__ __align__(256) fp16 g_mpi_h [(size_t)ROWS_ * M_];
__device__ __align__(256) fp16 g_m1_h  [(size_t)CROWS_ * M_];
__device__ __align__(256) fp16 g_h_h   [(size_t)CROWS_ * M_];

// ---------------------------------------------------------------------------
// helpers
// ---------------------------------------------------------------------------
__device__ __forceinline__ uint32_t smem_u32(const void* p) {
    uint32_t a;
    asm("{ .reg .u64 t; cvta.to.shared.u64 t, %1; cvt.u32.u64 %0, t; }"
        : "=r"(a) : "l"(p));
    return a;
}
__device__ __forceinline__ void cp16(uint32_t dst, const void* src) {
    asm volatile("cp.async.cg.shared.global [%0], [%1], 16;"
                 :: "r"(dst), "l"(src) : "memory");
}
#define CP_COMMIT() asm volatile("cp.async.commit_group;" ::: "memory")
#define CP_WAIT()   asm volatile("cp.async.wait_group 1;"  ::: "memory")

__device__ __forceinline__ void ldsm4(uint32_t* r, uint32_t a) {
    asm volatile("ldmatrix.sync.aligned.m8n8.x4.shared.b16 {%0,%1,%2,%3}, [%4];"
        : "=r"(r[0]), "=r"(r[1]), "=r"(r[2]), "=r"(r[3]) : "r"(a));
}
__device__ __forceinline__ void ldsm4t(uint32_t* r, uint32_t a) {
    asm volatile("ldmatrix.sync.aligned.m8n8.x4.trans.shared.b16 {%0,%1,%2,%3}, [%4];"
        : "=r"(r[0]), "=r"(r[1]), "=r"(r[2]), "=r"(r[3]) : "r"(a));
}
__device__ __forceinline__ void mma16816(float* c, const uint32_t* a, const uint32_t* b) {
    asm volatile(
        "mma.sync.aligned.m16n8k16.row.col.f32.f16.f16.f32 "
        "{%0,%1,%2,%3}, {%4,%5,%6,%7}, {%8,%9}, {%0,%1,%2,%3};"
        : "+f"(c[0]), "+f"(c[1]), "+f"(c[2]), "+f"(c[3])
        : "r"(a[0]), "r"(a[1]), "r"(a[2]), "r"(a[3]), "r"(b[0]), "r"(b[1]));
}

// fast tanh via MUFU: tanh(x) = 1 - 2/(e^{2x}+1)
__device__ __forceinline__ float ftanh(float x) {
    float e = __expf(2.f * x);
    return 1.f - __fdividef(2.f, e + 1.f);
}

// ---------------------------------------------------------------------------
// cvt6_kernel: fused fp32 -> fp16.  Regions 0..4 contiguous (inputs + 4
// weights).  Region 5 = memory -> mpi (strided) PLUS gate dot-product
// partials (warp-reduced; region start is warp- and row-aligned).
// ---------------------------------------------------------------------------
__global__ void cvt6_kernel(const float* __restrict__ s0, fp16* __restrict__ d0, int e0,
                            const float* __restrict__ s1, fp16* __restrict__ d1, int e1,
                            const float* __restrict__ s2, fp16* __restrict__ d2, int e2,
                            const float* __restrict__ s3, fp16* __restrict__ d3, int e3,
                            const float* __restrict__ s4, fp16* __restrict__ d4, int e4,
                            const float* __restrict__ mem, fp16* __restrict__ mpi,
                            const float* __restrict__ kgm, float* __restrict__ gpart,
                            int e5)
{
    int i = blockIdx.x * blockDim.x + threadIdx.x;
    if (i >= e5) return;
    if (i >= e4) {
        int j = i - e4;                    // float4 index into memory
        float4 v = __ldg((const float4*)mem + j);
        int row    = j >> 8;               // 256 float4 per row
        int within = (j & 255) << 1;       // fp162-pair index within row
        int b = row >> 3, s = row & 7;
        fp162* D = (fp162*)mpi + (((size_t)(b * SP1_ + s)) << 9) + within;
        D[0] = __floats2half2_rn(v.x, v.y);
        D[1] = __floats2half2_rn(v.z, v.w);

        // ---- fused gate partials: sum ftanh(mem)*kgm over this warp ----
        int mbase = (j & 255) << 2;        // element index within row
        float4 w0 = __ldg((const float4*)(kgm + 2 * mbase));      // 2m..2m+3
        float4 w1 = __ldg((const float4*)(kgm + 2 * mbase + 4));  // 2m+4..2m+7
        float t0 = ftanh(v.x), t1 = ftanh(v.y), t2 = ftanh(v.z), t3 = ftanh(v.w);
        float p0 = t0 * w0.x + t1 * w0.z + t2 * w1.x + t3 * w1.z;
        float p1 = t0 * w0.y + t1 * w0.w + t2 * w1.y + t3 * w1.w;
        #pragma unroll
        for (int o = 16; o; o >>= 1) {
            p0 += __shfl_xor_sync(0xffffffffu, p0, o);
            p1 += __shfl_xor_sync(0xffffffffu, p1, o);
        }
        if ((threadIdx.x & 31) == 0) {
            int wslot = (j >> 5) & 7;      // warp slot within row
            gpart[row * 16 + wslot * 2 + 0] = p0;
            gpart[row * 16 + wslot * 2 + 1] = p1;
        }
        return;
    }
    const float* s; fp16* d; int base;
    if      (i < e0) { s = s0; d = d0; base = 0;  }
    else if (i < e1) { s = s1; d = d1; base = e0; }
    else if (i < e2) { s = s2; d = d2; base = e1; }
    else if (i < e3) { s = s3; d = d3; base = e2; }
    else             { s = s4; d = d4; base = e3; }
    int j = i - base;
    float4 v = __ldg((const float4*)s + j);
    fp162* D = (fp162*)d + 2 * j;
    D[0] = __floats2half2_rn(v.x, v.y);
    D[1] = __floats2half2_rn(v.z, v.w);
}

// ---------------------------------------------------------------------------
// finalize_gates: one thread per (b,s) row.
// ---------------------------------------------------------------------------
__global__ void finalize_gates(const float* __restrict__ gpart,
                               const float* __restrict__ gi,
                               const float* __restrict__ bgm,
                               float* __restrict__ gates)
{
    int bs = blockIdx.x * blockDim.x + threadIdx.x;
    if (bs >= CROWS_) return;
    int b = bs >> 3;
    const float4* p = (const float4*)(gpart + bs * 16);
    float4 a = p[0], c = p[1], d2 = p[2], e = p[3];
    float G0 = (a.x + a.z) + (c.x + c.z) + (d2.x + d2.z) + (e.x + e.z);
    float G1 = (a.y + a.w) + (c.y + c.w) + (d2.y + d2.w) + (e.y + e.w);
    G0 += bgm[0] + gi[2 * b + 0];
    G1 += bgm[1] + gi[2 * b + 1] + 1.0f;
    gates[2 * bs + 0] = 1.f / (1.f + __expf(-G0));
    gates[2 * bs + 1] = 1.f / (1.f + __expf(-G1));
}

// ---------------------------------------------------------------------------
// fp16 HMMA GEMM (unchanged from R15)
// MODE 1: relu(+bias) -> fp16;  MODE 3: fp16 out;
// MODE 4: gated output;         MODE 5: fp32 out + fp16 into mpi row m*9+8
// ---------------------------------------------------------------------------
#define AST     144u
#define BST     272u
#define OFF_B   18432u
#define BUFSZ   35840u
#define NSTAGE  3
#define DSMEM   (NSTAGE * 35840)

template<int MODE>
__global__ __launch_bounds__(512)
void hgemm_kernel(const fp16* __restrict__ Ah, const fp16* __restrict__ Bh,
                  const float* __restrict__ bias,
                  const float* __restrict__ Rf,
                  const float* __restrict__ Gmem,
                  const float* __restrict__ Gates,
                  float* __restrict__ Cf, fp16* __restrict__ Ch,
                  int N, int K)
{
    extern __shared__ char sm_[];
    const uint32_t sbase = smem_u32(sm_);

    const int tid  = threadIdx.x;
    const int wid  = tid >> 5;
    const int lane = tid & 31;
    const int wm   = (wid & 3) << 5;
    const int wn   = (wid >> 2) << 5;
    const int bm   = blockIdx.y << 7;
    const int bn   = blockIdx.x << 7;

    const int arow = tid >> 2, aseg = tid & 3;
    const int brow = tid >> 4, bseg = tid & 15;

    const fp16* Ap = Ah + (size_t)(bm + arow) * K + (aseg << 3);
    const fp16* Bp = Bh + (size_t)brow * N + bn + (bseg << 3);
    const uint32_t aDst  = (uint32_t)arow * AST + (uint32_t)(aseg << 4);
    const uint32_t bDst  = (uint32_t)brow * BST + (uint32_t)(bseg << 4);
    const size_t  bRow2  = (size_t)32 * N;
    const uint32_t bDst2 = bDst + 32u * BST;

    const int nchunk = K >> 6;

    float acc[2][4][4];
    #pragma unroll
    for (int i = 0; i < 2; i++)
        #pragma unroll
        for (int j = 0; j < 4; j++)
            #pragma unroll
            for (int k = 0; k < 4; k++) acc[i][j][k] = 0.f;

    #pragma unroll
    for (int s = 0; s < NSTAGE - 1; s++) {
        const uint32_t sb = sbase + (uint32_t)s * BUFSZ;
        cp16(sb + aDst,        Ap + (s << 6));
        cp16(sb + aDst + 64u,  Ap + (s << 6) + 32);
        cp16(sb + OFF_B + bDst,  Bp + (size_t)(s << 6) * N);
        cp16(sb + OFF_B + bDst2, Bp + bRow2 + (size_t)(s << 6) * N);
        CP_COMMIT();
    }

    const uint32_t aOffBase = (uint32_t)(wm + (lane & 15)) * AST
                            + (uint32_t)((lane >> 4) << 4);
    const uint32_t bOffBase = (uint32_t)(lane & 15) * BST
                            + (uint32_t)(wn << 1) + (uint32_t)((lane >> 4) << 4);

    #pragma unroll 1
    for (int c = 0; c < nchunk; c++) {
        CP_WAIT();
        __syncthreads();

        const uint32_t tb = sbase + (uint32_t)(c % NSTAGE) * BUFSZ;

        #pragma unroll
        for (int ks = 0; ks < 4; ks++) {
            uint32_t ra[2][4], rb[2][4];
            const uint32_t aAd = tb + aOffBase + (uint32_t)(ks << 5);
            ldsm4(ra[0], aAd);
            ldsm4(ra[1], aAd + 16u * AST);
            const uint32_t bAd = tb + OFF_B + bOffBase + (uint32_t)(ks << 4) * BST;
            ldsm4t(rb[0], bAd);
            ldsm4t(rb[1], bAd + 32u);
            #pragma unroll
            for (int mt = 0; mt < 2; mt++)
                #pragma unroll
                for (int nt = 0; nt < 4; nt++)
                    mma16816(acc[mt][nt], ra[mt], &rb[nt >> 1][(nt & 1) << 1]);
        }

        const int cn = c + NSTAGE - 1;
        if (cn < nchunk) {
            const uint32_t nb = sbase + (uint32_t)(cn % NSTAGE) * BUFSZ;
            cp16(nb + aDst,        Ap + (cn << 6));
            cp16(nb + aDst + 64u,  Ap + (cn << 6) + 32);
            cp16(nb + OFF_B + bDst,  Bp + (size_t)(cn << 6) * N);
            cp16(nb + OFF_B + bDst2, Bp + bRow2 + (size_t)(cn << 6) * N);
        }
        CP_COMMIT();
    }

    // ---- epilogue ----
    #pragma unroll
    for (int mt = 0; mt < 2; mt++) {
        float ig0 = 0.f, fg0 = 0.f, ig1 = 0.f, fg1 = 0.f;
        if (MODE == 4) {
            const int mA = bm + wm + (mt << 4) + (lane >> 2);
            float2 gA = *(const float2*)(Gates + 2 * mA);
            float2 gB = *(const float2*)(Gates + 2 * (mA + 8));
            ig0 = gA.x; fg0 = gA.y;
            ig1 = gB.x; fg1 = gB.y;
        }
        #pragma unroll
        for (int nt = 0; nt < 4; nt++) {
            const int m = bm + wm + (mt << 4) + (lane >> 2);
            const int n = bn + wn + (nt << 3) + ((lane & 3) << 1);
            const float b0 = __ldg(&bias[n]);
            const float b1 = __ldg(&bias[n + 1]);
            float2 v0, v1;
            v0.x = acc[mt][nt][0] + b0;  v0.y = acc[mt][nt][1] + b1;
            v1.x = acc[mt][nt][2] + b0;  v1.y = acc[mt][nt][3] + b1;
            const size_t i0 = (size_t)m * N + n;
            const size_t i1 = (size_t)(m + 8) * N + n;
            if (MODE == 1) {
                v0.x = fmaxf(v0.x, 0.f); v0.y = fmaxf(v0.y, 0.f);
                v1.x = fmaxf(v1.x, 0.f); v1.y = fmaxf(v1.y, 0.f);
                *(fp162*)(Ch + i0) = __floats2half2_rn(v0.x, v0.y);
                *(fp162*)(Ch + i1) = __floats2half2_rn(v1.x, v1.y);
            }
            if (MODE == 3) {
                *(fp162*)(Ch + i0) = __floats2half2_rn(v0.x, v0.y);
                *(fp162*)(Ch + i1) = __floats2half2_rn(v1.x, v1.y);
            }
            if (MODE == 4) {
                float2 r0 = *(const float2*)(Rf + i0);
                float2 r1 = *(const float2*)(Rf + i1);
                float2 w0 = *(const float2*)(Gmem + i0);
                float2 w1 = *(const float2*)(Gmem + i1);
                float2 o0, o1;
                o0.x = fmaf(ig0, ftanh(v0.x + r0.x), fg0 * w0.x);
                o0.y = fmaf(ig0, ftanh(v0.y + r0.y), fg0 * w0.y);
                o1.x = fmaf(ig1, ftanh(v1.x + r1.x), fg1 * w1.x);
                o1.y = fmaf(ig1, ftanh(v1.y + r1.y), fg1 * w1.y);
                *(float2*)(Cf + i0) = o0;
                *(float2*)(Cf + i1) = o1;
            }
            if (MODE == 5) {
                *(float2*)(Cf + i0) = v0;
                *(float2*)(Cf + i1) = v1;
                const size_t p0 = ((size_t)m * SP1_ + S_) * M_ + n;
                const size_t p1 = ((size_t)(m + 8) * SP1_ + S_) * M_ + n;
                *(fp162*)(Ch + p0) = __floats2half2_rn(v0.x, v0.y);
                *(fp162*)(Ch + p1) = __floats2half2_rn(v1.x, v1.y);
            }
        }
    }
}

// ---------------------------------------------------------------------------
// gi[b,0:2] = x[b,:] @ kernel_gi + bias_gi
// ---------------------------------------------------------------------------
__global__ __launch_bounds__(128)
void gi_kernel(const float* __restrict__ x,
               const float* __restrict__ kgi,
               const float* __restrict__ bgi,
               float* __restrict__ gi)
{
    const int b   = blockIdx.x;
    const int tid = threadIdx.x;
    const float* xr = x + (size_t)b * M_;
    float g0 = 0.f, g1 = 0.f;
    for (int m = tid; m < M_; m += 128) {
        float xv = xr[m];
        g0 = fmaf(xv, kgi[2 * m + 0], g0);
        g1 = fmaf(xv, kgi[2 * m + 1], g1);
    }
    #pragma unroll
    for (int o = 16; o; o >>= 1) {
        g0 += __shfl_xor_sync(0xffffffffu, g0, o);
        g1 += __shfl_xor_sync(0xffffffffu, g1, o);
    }
    __shared__ float s0[4], s1[4];
    int w = tid >> 5, lane = tid & 31;
    if (lane == 0) { s0[w] = g0; s1[w] = g1; }
    __syncthreads();
    if (tid == 0) {
        gi[2 * b + 0] = s0[0] + s0[1] + s0[2] + s0[3] + bgi[0];
        gi[2 * b + 1] = s1[0] + s1[1] + s1[2] + s1[3] + bgi[1];
    }
}

// ---------------------------------------------------------------------------
// Attention per (b,h): m1 = res + softmax(q k^T) v   (compacted rows s<8)
// ---------------------------------------------------------------------------
__global__ __launch_bounds__(256)
void attn_kernel(const fp16* __restrict__ qkv,
                 const float* __restrict__ mem,
                 const float* __restrict__ x,
                 fp16* __restrict__ m1h, float* __restrict__ m1f)
{
    const int bh = blockIdx.x;
    const int b  = bh >> 3;
    const int h  = bh & 7;

    __shared__ float q [SP1_][128];
    __shared__ float kk[SP1_][128];
    __shared__ float vv[SP1_][128];
    __shared__ float sc[SP1_][SP1_];

    const float scale = rsqrtf((float)QKV_);
    const int tid = threadIdx.x;

    for (int i = tid; i < SP1_ * 64; i += 256) {
        int s = i >> 6, d = (i & 63) << 1;
        const fp16* base = qkv + ((size_t)(b * SP1_ + s)) * TOT_ + h * QKV_;
        fp162 qv  = *(const fp162*)(base + d);
        fp162 kv  = *(const fp162*)(base + 128 + d);
        fp162 vv2 = *(const fp162*)(base + 256 + d);
        q [s][d]     = __half2float(qv.x) * scale;
        q [s][d + 1] = __half2float(qv.y) * scale;
        kk[s][d]     = __half2float(kv.x);
        kk[s][d + 1] = __half2float(kv.y);
        vv[s][d]     = __half2float(vv2.x);
        vv[s][d + 1] = __half2float(vv2.y);
    }
    __syncthreads();

    const int w = tid >> 5, lane = tid & 31;
    for (int idx = w; idx < SP1_ * SP1_; idx += 8) {
        int i = idx / SP1_, j = idx - i * SP1_;
        float s = 0.f;
        for (int d = lane; d < 128; d += 32) s = fmaf(q[i][d], kk[j][d], s);
        #pragma unroll
        for (int o = 16; o; o >>= 1) s += __shfl_xor_sync(0xffffffffu, s, o);
        if (lane == 0) sc[i][j] = s;
    }
    __syncthreads();

    if (tid < SP1_) {
        float mx = -1e30f;
        #pragma unroll
        for (int j = 0; j < SP1_; j++) mx = fmaxf(mx, sc[tid][j]);
        float e[SP1_], sum = 0.f;
        #pragma unroll
        for (int j = 0; j < SP1_; j++) { e[j] = expf(sc[tid][j] - mx); sum += e[j]; }
        float inv = 1.f / sum;
        #pragma unroll
        for (int j = 0; j < SP1_; j++) sc[tid][j] = e[j] * inv;
    }
    __syncthreads();

    for (int i = tid; i < S_ * 64; i += 256) {
        int s  = i >> 6;
        int d  = (i & 63) << 1;
        float a0 = 0.f, a1 = 0.f;
        #pragma unroll
        for (int j = 0; j < SP1_; j++) {
            a0 = fmaf(sc[s][j], vv[j][d],     a0);
            a1 = fmaf(sc[s][j], vv[j][d + 1], a1);
        }
        const float* src = mem + (((size_t)b * S_ + s) << 10);
        float2 r = *(const float2*)(src + h * 128 + d);
        float v0 = r.x + a0;
        float v1 = r.y + a1;
        size_t o = ((size_t)(b * S_ + s)) * M_ + h * 128 + d;
        *(fp162*)(m1h + o) = __floats2half2_rn(v0, v1);
        *(float2*)(m1f + o) = make_float2(v0, v1);
    }
}

// ---------------------------------------------------------------------------
// kernel_launch
// ---------------------------------------------------------------------------
extern "C" void kernel_launch(void* const* d_in, const int* in_sizes, int n_in,
                              void* d_out, int out_size)
{
    const float* inputs   = (const float*)d_in[0];
    const float* memory   = (const float*)d_in[1];
    const float* k_qkv    = (const float*)d_in[2];
    const float* b_qkv    = (const float*)d_in[3];
    const float* k_gi     = (const float*)d_in[4];
    const float* b_gi     = (const float*)d_in[5];
    const float* k_gm     = (const float*)d_in[6];
    const float* b_gm     = (const float*)d_in[7];
    const float* k_in     = (const float*)d_in[8];
    const float* b_in     = (const float*)d_in[9];
    const float* mlp_k0   = (const float*)d_in[10];
    const float* mlp_b0   = (const float*)d_in[11];
    const float* mlp_k1   = (const float*)d_in[12];
    const float* mlp_b1   = (const float*)d_in[13];
    float* out = (float*)d_out;

    float *px, *pm1f, *pgi, *pgates, *pgpart;
    fp16 *pqkvh, *pinh, *pw, *pmpih, *pm1h, *phh;
    cudaGetSymbolAddress((void**)&px,     g_x);
    cudaGetSymbolAddress((void**)&pm1f,   g_m1f);
    cudaGetSymbolAddress((void**)&pgi,    g_gi);
    cudaGetSymbolAddress((void**)&pgates, g_gates);
    cudaGetSymbolAddress((void**)&pgpart, g_gpart);
    cudaGetSymbolAddress((void**)&pqkvh,  g_qkv_h);
    cudaGetSymbolAddress((void**)&pinh,   g_in_h);
    cudaGetSymbolAddress((void**)&pw,     g_w);
    cudaGetSymbolAddress((void**)&pmpih,  g_mpi_h);
    cudaGetSymbolAddress((void**)&pm1h,   g_m1_h);
    cudaGetSymbolAddress((void**)&phh,    g_h_h);

    const size_t MM = (size_t)M_ * M_;
    fp16 *kinW = pw;
    fp16 *kqkW = pw + MM;
    fp16 *k0W  = pw + 4 * MM;
    fp16 *k1W  = pw + 5 * MM;

    cudaFuncSetAttribute(hgemm_kernel<1>, cudaFuncAttributeMaxDynamicSharedMemorySize, DSMEM);
    cudaFuncSetAttribute(hgemm_kernel<3>, cudaFuncAttributeMaxDynamicSharedMemorySize, DSMEM);
    cudaFuncSetAttribute(hgemm_kernel<4>, cudaFuncAttributeMaxDynamicSharedMemorySize, DSMEM);
    cudaFuncSetAttribute(hgemm_kernel<5>, cudaFuncAttributeMaxDynamicSharedMemorySize, DSMEM);

    // 0. fused conversion + gate partials (one launch)
    {
        const int n_in4 = B_ * M_ / 4;
        const int n_1M4 = (int)(MM / 4);
        const int n_3M4 = (int)(3 * MM / 4);
        const int n_mem4 = CROWS_ * M_ / 4;
        const int e0 = n_in4;
        const int e1 = e0 + n_1M4;
        const int e2 = e1 + n_3M4;
        const int e3 = e2 + n_1M4;
        const int e4 = e3 + n_1M4;          // 2097152: 256-aligned -> region-5
        const int e5 = e4 + n_mem4;         // warps are row-aligned
        cvt6_kernel<<<(e5 + 255) / 256, 256>>>(
            inputs, pinh, e0,
            k_in,   kinW, e1,
            k_qkv,  kqkW, e2,
            mlp_k0, k0W,  e3,
            mlp_k1, k1W,  e4,
            memory, pmpih, k_gm, pgpart, e5);
    }

    // 1. x = inputs @ kernel_in + bias_in  (fp32 out + fp16 into mpi row s==8)
    hgemm_kernel<5><<<dim3(M_ / 128, B_ / 128), 512, DSMEM>>>(
        pinh, kinW, b_in, nullptr, nullptr, nullptr, px, pmpih, M_, M_);

    // 2. gi + finalize gates
    gi_kernel<<<B_, 128>>>(px, k_gi, b_gi, pgi);
    finalize_gates<<<CROWS_ / 256, 256>>>(pgpart, pgi, b_gm, pgates);

    // 3. qkv = mpi @ kernel_qkv + bias_qkv   (fp16 out)
    hgemm_kernel<3><<<dim3(TOT_ / 128, ROWS_ / 128), 512, DSMEM>>>(
        pmpih, kqkW, b_qkv, nullptr, nullptr, nullptr, nullptr, pqkvh, TOT_, M_);

    // 4. attention + fp32 residual -> compacted m1 (fp16 + fp32)
    attn_kernel<<<B_ * H_, 256>>>(pqkvh, memory, px, pm1h, pm1f);

    // 5. h = relu(m1 @ mlp_k0 + mlp_b0) -> fp16
    hgemm_kernel<1><<<dim3(M_ / 128, CROWS_ / 128), 512, DSMEM>>>(
        pm1h, k0W, mlp_b0, nullptr, nullptr, nullptr, nullptr, phh, M_, M_);

    // 6. out = ig*tanh(m1 + h @ mlp_k1 + mlp_b1) + fg*mem   (fused gate)
    hgemm_kernel<4><<<dim3(M_ / 128, CROWS_ / 128), 512, DSMEM>>>(
        phh, k1W, mlp_b1, pm1f, memory, pgates, out, nullptr, M_, M_);
}

// round 17
// speedup vs baseline: 1.2450x; 1.0101x over previous
#include <cuda_runtime.h>
#include <cuda_fp16.h>
#include <math.h>
#include <stdint.h>

// ---------------------------------------------------------------------------
// RelationalMemoryCell  (B=2048, S=8, H=8, M=1024, QKV=384, TOT=3072)
// Round 17: R16 + m1f eliminated (MODE 6 reads fp16 m1h residual) +
// finalize_gates folded into gi_kernel.
// ---------------------------------------------------------------------------

#define B_     2048
#define S_     8
#define H_     8
#define M_     1024
#define QKV_   384
#define TOT_   3072
#define SP1_   9
#define ROWS_  (B_*SP1_)   // 18432
#define CROWS_ (B_*S_)     // 16384

typedef __half  fp16;
typedef __half2 fp162;

// ---- global scratch (allocation-free rule) ----
__device__ __align__(256) float g_x    [(size_t)B_    * M_];
__device__ __align__(256) float g_gi   [(size_t)B_ * 2];
__device__ __align__(256) float g_gates[(size_t)CROWS_ * 2];
__device__ __align__(256) float g_gpart[(size_t)CROWS_ * 16];

__device__ __align__(256) fp16 g_qkv_h [(size_t)ROWS_ * TOT_];
__device__ __align__(256) fp16 g_in_h  [(size_t)B_ * M_];
__device__ __align__(256) fp16 g_w     [(size_t)6 * M_ * M_];
__device__ __align__(256) fp16 g_mpi_h [(size_t)ROWS_ * M_];
__device__ __align__(256) fp16 g_m1_h  [(size_t)CROWS_ * M_];
__device__ __align__(256) fp16 g_h_h   [(size_t)CROWS_ * M_];

// ---------------------------------------------------------------------------
// helpers
// ---------------------------------------------------------------------------
__device__ __forceinline__ uint32_t smem_u32(const void* p) {
    uint32_t a;
    asm("{ .reg .u64 t; cvta.to.shared.u64 t, %1; cvt.u32.u64 %0, t; }"
        : "=r"(a) : "l"(p));
    return a;
}
__device__ __forceinline__ void cp16(uint32_t dst, const void* src) {
    asm volatile("cp.async.cg.shared.global [%0], [%1], 16;"
                 :: "r"(dst), "l"(src) : "memory");
}
#define CP_COMMIT() asm volatile("cp.async.commit_group;" ::: "memory")
#define CP_WAIT()   asm volatile("cp.async.wait_group 1;"  ::: "memory")

__device__ __forceinline__ void ldsm4(uint32_t* r, uint32_t a) {
    asm volatile("ldmatrix.sync.aligned.m8n8.x4.shared.b16 {%0,%1,%2,%3}, [%4];"
        : "=r"(r[0]), "=r"(r[1]), "=r"(r[2]), "=r"(r[3]) : "r"(a));
}
__device__ __forceinline__ void ldsm4t(uint32_t* r, uint32_t a) {
    asm volatile("ldmatrix.sync.aligned.m8n8.x4.trans.shared.b16 {%0,%1,%2,%3}, [%4];"
        : "=r"(r[0]), "=r"(r[1]), "=r"(r[2]), "=r"(r[3]) : "r"(a));
}
__device__ __forceinline__ void mma16816(float* c, const uint32_t* a, const uint32_t* b) {
    asm volatile(
        "mma.sync.aligned.m16n8k16.row.col.f32.f16.f16.f32 "
        "{%0,%1,%2,%3}, {%4,%5,%6,%7}, {%8,%9}, {%0,%1,%2,%3};"
        : "+f"(c[0]), "+f"(c[1]), "+f"(c[2]), "+f"(c[3])
        : "r"(a[0]), "r"(a[1]), "r"(a[2]), "r"(a[3]), "r"(b[0]), "r"(b[1]));
}

// fast tanh via MUFU: tanh(x) = 1 - 2/(e^{2x}+1)
__device__ __forceinline__ float ftanh(float x) {
    float e = __expf(2.f * x);
    return 1.f - __fdividef(2.f, e + 1.f);
}

// ---------------------------------------------------------------------------
// cvt6_kernel: fused fp32 -> fp16 + gate partials (unchanged from R16)
// ---------------------------------------------------------------------------
__global__ void cvt6_kernel(const float* __restrict__ s0, fp16* __restrict__ d0, int e0,
                            const float* __restrict__ s1, fp16* __restrict__ d1, int e1,
                            const float* __restrict__ s2, fp16* __restrict__ d2, int e2,
                            const float* __restrict__ s3, fp16* __restrict__ d3, int e3,
                            const float* __restrict__ s4, fp16* __restrict__ d4, int e4,
                            const float* __restrict__ mem, fp16* __restrict__ mpi,
                            const float* __restrict__ kgm, float* __restrict__ gpart,
                            int e5)
{
    int i = blockIdx.x * blockDim.x + threadIdx.x;
    if (i >= e5) return;
    if (i >= e4) {
        int j = i - e4;
        float4 v = __ldg((const float4*)mem + j);
        int row    = j >> 8;
        int within = (j & 255) << 1;
        int b = row >> 3, s = row & 7;
        fp162* D = (fp162*)mpi + (((size_t)(b * SP1_ + s)) << 9) + within;
        D[0] = __floats2half2_rn(v.x, v.y);
        D[1] = __floats2half2_rn(v.z, v.w);

        int mbase = (j & 255) << 2;
        float4 w0 = __ldg((const float4*)(kgm + 2 * mbase));
        float4 w1 = __ldg((const float4*)(kgm + 2 * mbase + 4));
        float t0 = ftanh(v.x), t1 = ftanh(v.y), t2 = ftanh(v.z), t3 = ftanh(v.w);
        float p0 = t0 * w0.x + t1 * w0.z + t2 * w1.x + t3 * w1.z;
        float p1 = t0 * w0.y + t1 * w0.w + t2 * w1.y + t3 * w1.w;
        #pragma unroll
        for (int o = 16; o; o >>= 1) {
            p0 += __shfl_xor_sync(0xffffffffu, p0, o);
            p1 += __shfl_xor_sync(0xffffffffu, p1, o);
        }
        if ((threadIdx.x & 31) == 0) {
            int wslot = (j >> 5) & 7;
            gpart[row * 16 + wslot * 2 + 0] = p0;
            gpart[row * 16 + wslot * 2 + 1] = p1;
        }
        return;
    }
    const float* s; fp16* d; int base;
    if      (i < e0) { s = s0; d = d0; base = 0;  }
    else if (i < e1) { s = s1; d = d1; base = e0; }
    else if (i < e2) { s = s2; d = d2; base = e1; }
    else if (i < e3) { s = s3; d = d3; base = e2; }
    else             { s = s4; d = d4; base = e3; }
    int j = i - base;
    float4 v = __ldg((const float4*)s + j);
    fp162* D = (fp162*)d + 2 * j;
    D[0] = __floats2half2_rn(v.x, v.y);
    D[1] = __floats2half2_rn(v.z, v.w);
}

// ---------------------------------------------------------------------------
// fp16 HMMA GEMM.
// MODE 1: relu(+bias) -> fp16;  MODE 3: fp16 out;
// MODE 5: fp32 out + fp16 into mpi row m*9+8;
// MODE 6: gated: v = toF32(Rh) + (.+bias); Cf = ig*ftanh(v) + fg*Gmem
// ---------------------------------------------------------------------------
#define AST     144u
#define BST     272u
#define OFF_B   18432u
#define BUFSZ   35840u
#define NSTAGE  3
#define DSMEM   (NSTAGE * 35840)

template<int MODE>
__global__ __launch_bounds__(512)
void hgemm_kernel(const fp16* __restrict__ Ah, const fp16* __restrict__ Bh,
                  const float* __restrict__ bias,
                  const fp16* __restrict__ Rh,
                  const float* __restrict__ Gmem,
                  const float* __restrict__ Gates,
                  float* __restrict__ Cf, fp16* __restrict__ Ch,
                  int N, int K)
{
    extern __shared__ char sm_[];
    const uint32_t sbase = smem_u32(sm_);

    const int tid  = threadIdx.x;
    const int wid  = tid >> 5;
    const int lane = tid & 31;
    const int wm   = (wid & 3) << 5;
    const int wn   = (wid >> 2) << 5;
    const int bm   = blockIdx.y << 7;
    const int bn   = blockIdx.x << 7;

    const int arow = tid >> 2, aseg = tid & 3;
    const int brow = tid >> 4, bseg = tid & 15;

    const fp16* Ap = Ah + (size_t)(bm + arow) * K + (aseg << 3);
    const fp16* Bp = Bh + (size_t)brow * N + bn + (bseg << 3);
    const uint32_t aDst  = (uint32_t)arow * AST + (uint32_t)(aseg << 4);
    const uint32_t bDst  = (uint32_t)brow * BST + (uint32_t)(bseg << 4);
    const size_t  bRow2  = (size_t)32 * N;
    const uint32_t bDst2 = bDst + 32u * BST;

    const int nchunk = K >> 6;

    float acc[2][4][4];
    #pragma unroll
    for (int i = 0; i < 2; i++)
        #pragma unroll
        for (int j = 0; j < 4; j++)
            #pragma unroll
            for (int k = 0; k < 4; k++) acc[i][j][k] = 0.f;

    #pragma unroll
    for (int s = 0; s < NSTAGE - 1; s++) {
        const uint32_t sb = sbase + (uint32_t)s * BUFSZ;
        cp16(sb + aDst,        Ap + (s << 6));
        cp16(sb + aDst + 64u,  Ap + (s << 6) + 32);
        cp16(sb + OFF_B + bDst,  Bp + (size_t)(s << 6) * N);
        cp16(sb + OFF_B + bDst2, Bp + bRow2 + (size_t)(s << 6) * N);
        CP_COMMIT();
    }

    const uint32_t aOffBase = (uint32_t)(wm + (lane & 15)) * AST
                            + (uint32_t)((lane >> 4) << 4);
    const uint32_t bOffBase = (uint32_t)(lane & 15) * BST
                            + (uint32_t)(wn << 1) + (uint32_t)((lane >> 4) << 4);

    #pragma unroll 1
    for (int c = 0; c < nchunk; c++) {
        CP_WAIT();
        __syncthreads();

        const uint32_t tb = sbase + (uint32_t)(c % NSTAGE) * BUFSZ;

        #pragma unroll
        for (int ks = 0; ks < 4; ks++) {
            uint32_t ra[2][4], rb[2][4];
            const uint32_t aAd = tb + aOffBase + (uint32_t)(ks << 5);
            ldsm4(ra[0], aAd);
            ldsm4(ra[1], aAd + 16u * AST);
            const uint32_t bAd = tb + OFF_B + bOffBase + (uint32_t)(ks << 4) * BST;
            ldsm4t(rb[0], bAd);
            ldsm4t(rb[1], bAd + 32u);
            #pragma unroll
            for (int mt = 0; mt < 2; mt++)
                #pragma unroll
                for (int nt = 0; nt < 4; nt++)
                    mma16816(acc[mt][nt], ra[mt], &rb[nt >> 1][(nt & 1) << 1]);
        }

        const int cn = c + NSTAGE - 1;
        if (cn < nchunk) {
            const uint32_t nb = sbase + (uint32_t)(cn % NSTAGE) * BUFSZ;
            cp16(nb + aDst,        Ap + (cn << 6));
            cp16(nb + aDst + 64u,  Ap + (cn << 6) + 32);
            cp16(nb + OFF_B + bDst,  Bp + (size_t)(cn << 6) * N);
            cp16(nb + OFF_B + bDst2, Bp + bRow2 + (size_t)(cn << 6) * N);
        }
        CP_COMMIT();
    }

    // ---- epilogue ----
    #pragma unroll
    for (int mt = 0; mt < 2; mt++) {
        float ig0 = 0.f, fg0 = 0.f, ig1 = 0.f, fg1 = 0.f;
        if (MODE == 6) {
            const int mA = bm + wm + (mt << 4) + (lane >> 2);
            float2 gA = *(const float2*)(Gates + 2 * mA);
            float2 gB = *(const float2*)(Gates + 2 * (mA + 8));
            ig0 = gA.x; fg0 = gA.y;
            ig1 = gB.x; fg1 = gB.y;
        }
        #pragma unroll
        for (int nt = 0; nt < 4; nt++) {
            const int m = bm + wm + (mt << 4) + (lane >> 2);
            const int n = bn + wn + (nt << 3) + ((lane & 3) << 1);
            const float b0 = __ldg(&bias[n]);
            const float b1 = __ldg(&bias[n + 1]);
            float2 v0, v1;
            v0.x = acc[mt][nt][0] + b0;  v0.y = acc[mt][nt][1] + b1;
            v1.x = acc[mt][nt][2] + b0;  v1.y = acc[mt][nt][3] + b1;
            const size_t i0 = (size_t)m * N + n;
            const size_t i1 = (size_t)(m + 8) * N + n;
            if (MODE == 1) {
                v0.x = fmaxf(v0.x, 0.f); v0.y = fmaxf(v0.y, 0.f);
                v1.x = fmaxf(v1.x, 0.f); v1.y = fmaxf(v1.y, 0.f);
                *(fp162*)(Ch + i0) = __floats2half2_rn(v0.x, v0.y);
                *(fp162*)(Ch + i1) = __floats2half2_rn(v1.x, v1.y);
            }
            if (MODE == 3) {
                *(fp162*)(Ch + i0) = __floats2half2_rn(v0.x, v0.y);
                *(fp162*)(Ch + i1) = __floats2half2_rn(v1.x, v1.y);
            }
            if (MODE == 6) {
                fp162 r0 = *(const fp162*)(Rh + i0);
                fp162 r1 = *(const fp162*)(Rh + i1);
                float2 w0 = *(const float2*)(Gmem + i0);
                float2 w1 = *(const float2*)(Gmem + i1);
                float2 o0, o1;
                o0.x = fmaf(ig0, ftanh(v0.x + __half2float(r0.x)), fg0 * w0.x);
                o0.y = fmaf(ig0, ftanh(v0.y + __half2float(r0.y)), fg0 * w0.y);
                o1.x = fmaf(ig1, ftanh(v1.x + __half2float(r1.x)), fg1 * w1.x);
                o1.y = fmaf(ig1, ftanh(v1.y + __half2float(r1.y)), fg1 * w1.y);
                *(float2*)(Cf + i0) = o0;
                *(float2*)(Cf + i1) = o1;
            }
            if (MODE == 5) {
                *(float2*)(Cf + i0) = v0;
                *(float2*)(Cf + i1) = v1;
                const size_t p0 = ((size_t)m * SP1_ + S_) * M_ + n;
                const size_t p1 = ((size_t)(m + 8) * SP1_ + S_) * M_ + n;
                *(fp162*)(Ch + p0) = __floats2half2_rn(v0.x, v0.y);
                *(fp162*)(Ch + p1) = __floats2half2_rn(v1.x, v1.y);
            }
        }
    }
}

// ---------------------------------------------------------------------------
// gi_kernel + fused gate finalize.  One 128-thread block per b.
// ---------------------------------------------------------------------------
__global__ __launch_bounds__(128)
void gi_kernel(const float* __restrict__ x,
               const float* __restrict__ kgi,
               const float* __restrict__ bgi,
               const float* __restrict__ gpart,
               const float* __restrict__ bgm,
               float* __restrict__ gates)
{
    const int b   = blockIdx.x;
    const int tid = threadIdx.x;
    const float* xr = x + (size_t)b * M_;
    float g0 = 0.f, g1 = 0.f;
    for (int m = tid; m < M_; m += 128) {
        float xv = xr[m];
        g0 = fmaf(xv, kgi[2 * m + 0], g0);
        g1 = fmaf(xv, kgi[2 * m + 1], g1);
    }
    #pragma unroll
    for (int o = 16; o; o >>= 1) {
        g0 += __shfl_xor_sync(0xffffffffu, g0, o);
        g1 += __shfl_xor_sync(0xffffffffu, g1, o);
    }
    __shared__ float s0[4], s1[4];
    __shared__ float gi0s, gi1s;
    int w = tid >> 5, lane = tid & 31;
    if (lane == 0) { s0[w] = g0; s1[w] = g1; }
    __syncthreads();
    if (tid == 0) {
        gi0s = s0[0] + s0[1] + s0[2] + s0[3] + bgi[0];
        gi1s = s1[0] + s1[1] + s1[2] + s1[3] + bgi[1] + 1.0f;  // FORGET_BIAS
    }
    __syncthreads();
    if (tid < S_) {
        int bs = b * S_ + tid;
        const float4* p = (const float4*)(gpart + bs * 16);
        float4 a = p[0], c = p[1], d2 = p[2], e = p[3];
        float G0 = (a.x + a.z) + (c.x + c.z) + (d2.x + d2.z) + (e.x + e.z);
        float G1 = (a.y + a.w) + (c.y + c.w) + (d2.y + d2.w) + (e.y + e.w);
        G0 += bgm[0] + gi0s;
        G1 += bgm[1] + gi1s;
        gates[2 * bs + 0] = 1.f / (1.f + __expf(-G0));
        gates[2 * bs + 1] = 1.f / (1.f + __expf(-G1));
    }
}

// ---------------------------------------------------------------------------
// Attention per (b,h): m1 = res + softmax(q k^T) v  -> fp16 only (compacted)
// ---------------------------------------------------------------------------
__global__ __launch_bounds__(256)
void attn_kernel(const fp16* __restrict__ qkv,
                 const float* __restrict__ mem,
                 const float* __restrict__ x,
                 fp16* __restrict__ m1h)
{
    const int bh = blockIdx.x;
    const int b  = bh >> 3;
    const int h  = bh & 7;

    __shared__ float q [SP1_][128];
    __shared__ float kk[SP1_][128];
    __shared__ float vv[SP1_][128];
    __shared__ float sc[SP1_][SP1_];

    const float scale = rsqrtf((float)QKV_);
    const int tid = threadIdx.x;

    for (int i = tid; i < SP1_ * 64; i += 256) {
        int s = i >> 6, d = (i & 63) << 1;
        const fp16* base = qkv + ((size_t)(b * SP1_ + s)) * TOT_ + h * QKV_;
        fp162 qv  = *(const fp162*)(base + d);
        fp162 kv  = *(const fp162*)(base + 128 + d);
        fp162 vv2 = *(const fp162*)(base + 256 + d);
        q [s][d]     = __half2float(qv.x) * scale;
        q [s][d + 1] = __half2float(qv.y) * scale;
        kk[s][d]     = __half2float(kv.x);
        kk[s][d + 1] = __half2float(kv.y);
        vv[s][d]     = __half2float(vv2.x);
        vv[s][d + 1] = __half2float(vv2.y);
    }
    __syncthreads();

    const int w = tid >> 5, lane = tid & 31;
    for (int idx = w; idx < SP1_ * SP1_; idx += 8) {
        int i = idx / SP1_, j = idx - i * SP1_;
        float s = 0.f;
        for (int d = lane; d < 128; d += 32) s = fmaf(q[i][d], kk[j][d], s);
        #pragma unroll
        for (int o = 16; o; o >>= 1) s += __shfl_xor_sync(0xffffffffu, s, o);
        if (lane == 0) sc[i][j] = s;
    }
    __syncthreads();

    if (tid < SP1_) {
        float mx = -1e30f;
        #pragma unroll
        for (int j = 0; j < SP1_; j++) mx = fmaxf(mx, sc[tid][j]);
        float e[SP1_], sum = 0.f;
        #pragma unroll
        for (int j = 0; j < SP1_; j++) { e[j] = expf(sc[tid][j] - mx); sum += e[j]; }
        float inv = 1.f / sum;
        #pragma unroll
        for (int j = 0; j < SP1_; j++) sc[tid][j] = e[j] * inv;
    }
    __syncthreads();

    for (int i = tid; i < S_ * 64; i += 256) {
        int s  = i >> 6;
        int d  = (i & 63) << 1;
        float a0 = 0.f, a1 = 0.f;
        #pragma unroll
        for (int j = 0; j < SP1_; j++) {
            a0 = fmaf(sc[s][j], vv[j][d],     a0);
            a1 = fmaf(sc[s][j], vv[j][d + 1], a1);
        }
        const float* src = mem + (((size_t)b * S_ + s) << 10);
        float2 r = *(const float2*)(src + h * 128 + d);
        size_t o = ((size_t)(b * S_ + s)) * M_ + h * 128 + d;
        *(fp162*)(m1h + o) = __floats2half2_rn(r.x + a0, r.y + a1);
    }
}

// ---------------------------------------------------------------------------
// kernel_launch
// ---------------------------------------------------------------------------
extern "C" void kernel_launch(void* const* d_in, const int* in_sizes, int n_in,
                              void* d_out, int out_size)
{
    const float* inputs   = (const float*)d_in[0];
    const float* memory   = (const float*)d_in[1];
    const float* k_qkv    = (const float*)d_in[2];
    const float* b_qkv    = (const float*)d_in[3];
    const float* k_gi     = (const float*)d_in[4];
    const float* b_gi     = (const float*)d_in[5];
    const float* k_gm     = (const float*)d_in[6];
    const float* b_gm     = (const float*)d_in[7];
    const float* k_in     = (const float*)d_in[8];
    const float* b_in     = (const float*)d_in[9];
    const float* mlp_k0   = (const float*)d_in[10];
    const float* mlp_b0   = (const float*)d_in[11];
    const float* mlp_k1   = (const float*)d_in[12];
    const float* mlp_b1   = (const float*)d_in[13];
    float* out = (float*)d_out;

    float *px, *pgi, *pgates, *pgpart;
    fp16 *pqkvh, *pinh, *pw, *pmpih, *pm1h, *phh;
    cudaGetSymbolAddress((void**)&px,     g_x);
    cudaGetSymbolAddress((void**)&pgi,    g_gi);
    cudaGetSymbolAddress((void**)&pgates, g_gates);
    cudaGetSymbolAddress((void**)&pgpart, g_gpart);
    cudaGetSymbolAddress((void**)&pqkvh,  g_qkv_h);
    cudaGetSymbolAddress((void**)&pinh,   g_in_h);
    cudaGetSymbolAddress((void**)&pw,     g_w);
    cudaGetSymbolAddress((void**)&pmpih,  g_mpi_h);
    cudaGetSymbolAddress((void**)&pm1h,   g_m1_h);
    cudaGetSymbolAddress((void**)&phh,    g_h_h);
    (void)pgi;

    const size_t MM = (size_t)M_ * M_;
    fp16 *kinW = pw;
    fp16 *kqkW = pw + MM;
    fp16 *k0W  = pw + 4 * MM;
    fp16 *k1W  = pw + 5 * MM;

    cudaFuncSetAttribute(hgemm_kernel<1>, cudaFuncAttributeMaxDynamicSharedMemorySize, DSMEM);
    cudaFuncSetAttribute(hgemm_kernel<3>, cudaFuncAttributeMaxDynamicSharedMemorySize, DSMEM);
    cudaFuncSetAttribute(hgemm_kernel<5>, cudaFuncAttributeMaxDynamicSharedMemorySize, DSMEM);
    cudaFuncSetAttribute(hgemm_kernel<6>, cudaFuncAttributeMaxDynamicSharedMemorySize, DSMEM);

    // 0. fused conversion + gate partials
    {
        const int n_in4 = B_ * M_ / 4;
        const int n_1M4 = (int)(MM / 4);
        const int n_3M4 = (int)(3 * MM / 4);
        const int n_mem4 = CROWS_ * M_ / 4;
        const int e0 = n_in4;
        const int e1 = e0 + n_1M4;
        const int e2 = e1 + n_3M4;
        const int e3 = e2 + n_1M4;
        const int e4 = e3 + n_1M4;
        const int e5 = e4 + n_mem4;
        cvt6_kernel<<<(e5 + 255) / 256, 256>>>(
            inputs, pinh, e0,
            k_in,   kinW, e1,
            k_qkv,  kqkW, e2,
            mlp_k0, k0W,  e3,
            mlp_k1, k1W,  e4,
            memory, pmpih, k_gm, pgpart, e5);
    }

    // 1. x = inputs @ kernel_in + bias_in  (fp32 out + fp16 into mpi row s==8)
    hgemm_kernel<5><<<dim3(M_ / 128, B_ / 128), 512, DSMEM>>>(
        pinh, kinW, b_in, nullptr, nullptr, nullptr, px, pmpih, M_, M_);

    // 2. gi + gates (fused finalize)
    gi_kernel<<<B_, 128>>>(px, k_gi, b_gi, pgpart, b_gm, pgates);

    // 3. qkv = mpi @ kernel_qkv + bias_qkv   (fp16 out)
    hgemm_kernel<3><<<dim3(TOT_ / 128, ROWS_ / 128), 512, DSMEM>>>(
        pmpih, kqkW, b_qkv, nullptr, nullptr, nullptr, nullptr, pqkvh, TOT_, M_);

    // 4. attention + residual -> compacted m1 (fp16 only)
    attn_kernel<<<B_ * H_, 256>>>(pqkvh, memory, px, pm1h);

    // 5. h = relu(m1 @ mlp_k0 + mlp_b0) -> fp16
    hgemm_kernel<1><<<dim3(M_ / 128, CROWS_ / 128), 512, DSMEM>>>(
        pm1h, k0W, mlp_b0, nullptr, nullptr, nullptr, nullptr, phh, M_, M_);

    // 6. out = ig*tanh(m1h + h @ mlp_k1 + mlp_b1) + fg*mem   (fused gate)
    hgemm_kernel<6><<<dim3(M_ / 128, CROWS_ / 128), 512, DSMEM>>>(
        phh, k1W, mlp_b1, pm1h, memory, pgates, out, nullptr, M_, M_);
}